// round 10
// baseline (speedup 1.0000x reference)
#include <cuda_runtime.h>
#include <cuda.h>
#include <cstdint>

// Conv1dGroup as 129 tf32 tcgen05 GEMMs, shifted-accumulator scheme:
// per tile (128 t rows) x is loaded ONCE (3 f-blocks of 32); three TMEM
// accumulators Gk[r] = x[t0+r].W_k; epilogue combines
//   out[t0+r] = G0[r-1] + G1[r] + G2[r+1] + bias
// via lane shuffles + smem boundary exchange + cross-tile carry/pending.
// A traffic = x bytes exactly (no K=3 unfold duplication).

#define CB 4
#define CT 512
#define CG 129
#define CF 96
#define CO 96
#define CK 3

#define ACOLT 12288                 // B bytes per 32-K atom col
#define NKB 9                       // 9 K blocks (K=288)
#define B_BYTES (NKB * ACOLT)       // 110592
#define NBUF 7
#define CHUNKS 48                   // 16 tiles x 3 f-blocks
#define NTHREADS 192                // 4 epi + 1 mma + 1 tma warps

#define SWZ(x) ((x) ^ (((x) >> 3) & 0x70))
#define IDESC_T ((1u<<4) | (2u<<7) | (2u<<10) | ((CO/8)<<17) | ((128/16)<<24))

// SMEM map (bytes)
#define SM_B       0
#define SM_A       110592           // 7 x 16384 -> ends 225280
#define SM_BIAS    225280           // 384
#define SM_EXG0    225664           // 4 warps x 32 f = 512
#define SM_EXG2    226176           // 512
#define SM_CARRY   226688           // 2 parity x 96 f = 768
#define SM_PEND    227456           // 768
#define SM_TMEMPTR 228224
#define SM_MBAR    228240
// full[7]@0..55  empty[7]@56..111  tile@112  epi@120  bok@128
#define SMEM_TOTAL 228480

#if defined(__CUDA_ARCH_FEAT_SM103_ALL) || defined(__CUDA_ARCH_FEAT_SM100_ALL)
#define CONV_HAS_TCGEN05 1
#else
#define CONV_HAS_TCGEN05 0
#endif

__device__ __align__(16) unsigned char g_wt[CG * B_BYTES];

static __device__ __forceinline__ uint32_t smem_u32(const void* p) {
    uint32_t a;
    asm("{ .reg .u64 t; cvta.to.shared.u64 t, %1; cvt.u32.u64 %0, t; }" : "=r"(a) : "l"(p));
    return a;
}

#define MBARRIER_INIT(addr, cnt) \
    asm volatile("mbarrier.init.shared.b64 [%0], %1;" :: "r"(addr), "r"(cnt) : "memory")
#define MBARRIER_INVAL(addr) \
    asm volatile("mbarrier.inval.shared.b64 [%0];" :: "r"(addr) : "memory")
#define MBARRIER_ARRIVE(addr) \
    asm volatile("mbarrier.arrive.shared.b64 _, [%0];" :: "r"((uint32_t)(addr)) : "memory")
#define MBARRIER_EXPECT_TX(addr, bytes) \
    asm volatile("mbarrier.arrive.expect_tx.shared.b64 _, [%0], %1;" \
                 :: "r"((uint32_t)(addr)), "r"((uint32_t)(bytes)) : "memory")
#define MBAR_WAIT(addr, parity, SEM) do {                                          \
    asm volatile(                                                                  \
        "{\n\t.reg .pred P;\n\t"                                                   \
        "WL_%=:\n\t"                                                               \
        "mbarrier.try_wait.parity." SEM ".cta.shared::cta.b64 P, [%0], %1, 0x989680;\n\t" \
        "@P bra.uni WD_%=;\n\t"                                                    \
        "bra.uni WL_%=;\n\t"                                                       \
        "WD_%=:\n\t}"                                                              \
        :: "r"((uint32_t)(addr)), "r"((uint32_t)(parity)) : "memory");             \
} while (0)
#define MBARRIER_WAIT_PARITY(a, p)  MBAR_WAIT(a, p, "acquire")
#define MBARRIER_WAIT_RELAXED(a, p) MBAR_WAIT(a, p, "relaxed")

#if CONV_HAS_TCGEN05

#define TCGEN05_ALLOC(smaddr, ncols) \
    asm volatile("tcgen05.alloc.cta_group::1.sync.aligned.shared::cta.b32 [%0], %1;" \
                 :: "r"((uint32_t)(smaddr)), "r"((uint32_t)(ncols)) : "memory")
#define TCGEN05_DEALLOC(tm, ncols) \
    asm volatile("tcgen05.dealloc.cta_group::1.sync.aligned.b32 %0, %1;" \
                 :: "r"(tm), "r"((uint32_t)(ncols)))
#define TCGEN05_COMMIT(mbar) \
    asm volatile("tcgen05.commit.cta_group::1.mbarrier::arrive::one.shared::cluster.b64 [%0];" \
                 :: "r"((uint32_t)(mbar)) : "memory")
#define TCGEN05_WAIT_LD() asm volatile("tcgen05.wait::ld.sync.aligned;" ::: "memory")
#define TCGEN05_FENCE_BEFORE() asm volatile("tcgen05.fence::before_thread_sync;" ::: "memory")
#define TCGEN05_FENCE_AFTER()  asm volatile("tcgen05.fence::after_thread_sync;" ::: "memory")

#define TCGEN05_LD_32X32B_X32(r, tmaddr) \
    asm volatile( \
        "tcgen05.ld.sync.aligned.32x32b.x32.b32 " \
        "{%0, %1, %2, %3, %4, %5, %6, %7, " \
        " %8, %9, %10, %11, %12, %13, %14, %15, " \
        " %16, %17, %18, %19, %20, %21, %22, %23, " \
        " %24, %25, %26, %27, %28, %29, %30, %31}, [%32];" \
        : "=r"((r)[0]),  "=r"((r)[1]),  "=r"((r)[2]),  "=r"((r)[3]), \
          "=r"((r)[4]),  "=r"((r)[5]),  "=r"((r)[6]),  "=r"((r)[7]), \
          "=r"((r)[8]),  "=r"((r)[9]),  "=r"((r)[10]), "=r"((r)[11]), \
          "=r"((r)[12]), "=r"((r)[13]), "=r"((r)[14]), "=r"((r)[15]), \
          "=r"((r)[16]), "=r"((r)[17]), "=r"((r)[18]), "=r"((r)[19]), \
          "=r"((r)[20]), "=r"((r)[21]), "=r"((r)[22]), "=r"((r)[23]), \
          "=r"((r)[24]), "=r"((r)[25]), "=r"((r)[26]), "=r"((r)[27]), \
          "=r"((r)[28]), "=r"((r)[29]), "=r"((r)[30]), "=r"((r)[31]) \
        : "r"(tmaddr))

#define TMA_LOAD_4D(smaddr, tmap, c0, c1, c2, c3, mbar) \
    asm volatile( \
        "cp.async.bulk.tensor.4d.shared::cta.global.tile.mbarrier::complete_tx::bytes " \
        "[%0], [%1, {%2, %3, %4, %5}], [%6];" \
        :: "r"((uint32_t)(smaddr)), "l"(tmap), "r"((int)(c0)), "r"((int)(c1)), \
           "r"((int)(c2)), "r"((int)(c3)), "r"((uint32_t)(mbar)) : "memory")

#define BULK_G2S(smaddr, gptr, bytes, mbar) \
    asm volatile( \
        "cp.async.bulk.shared::cta.global.mbarrier::complete_tx::bytes [%0], [%1], %2, [%3];" \
        :: "r"((uint32_t)(smaddr)), "l"(gptr), "r"((uint32_t)(bytes)), \
           "r"((uint32_t)(mbar)) : "memory")

static constexpr uint64_t SMEM_DESC_BASE_SW128 =
    (uint64_t(2) << 61) | (uint64_t(1) << 46) | (uint64_t(64) << 32) | (uint64_t(1) << 16);

static __device__ __forceinline__ uint64_t make_desc(uint32_t smaddr) {
    return SMEM_DESC_BASE_SW128 | ((uint64_t)(smaddr >> 4) & 0x3FFF);
}

static __device__ __forceinline__ void mma_tf32_ss(uint32_t d, uint64_t a, uint64_t b,
                                                   uint32_t idesc, uint32_t en) {
    asm volatile(
        "{\n\t.reg .pred p;\n\t"
        "setp.ne.u32 p, %4, 0;\n\t"
        "tcgen05.mma.cta_group::1.kind::tf32 [%0], %1, %2, %3, p;\n\t}"
        :: "r"(d), "l"(a), "l"(b), "r"(idesc), "r"(en) : "memory");
}

static __device__ __forceinline__ uint32_t elect_one() {
    uint32_t pred;
    asm volatile(
        "{\n\t.reg .pred p;\n\t"
        "elect.sync _|p, 0xFFFFFFFF;\n\t"
        "selp.b32 %0, 1, 0, p;\n\t}" : "=r"(pred));
    return pred;
}

#endif // CONV_HAS_TCGEN05

// -------- pre-kernel: weights -> tf32 (rna) in MMA SMEM layout --------

__global__ __launch_bounds__(256) void prep_w(const float* __restrict__ w) {
    int id = blockIdx.x * 256 + threadIdx.x;
    const int NTASK = CG * CO * 288;
    if (id >= NTASK) return;
    int K = id % 288;
    int o = (id / 288) % CO;
    int g = id / (288 * CO);
    int k = K / CF, f = K - CF * k;
    float v = w[(((size_t)(g * CO + o) * CF + f) * CK + k)];
    uint32_t t;
    asm("cvt.rna.tf32.f32 %0, %1;" : "=r"(t) : "f"(v));
    uint32_t addr = (uint32_t)g * B_BYTES + (K >> 5) * ACOLT + (o >> 3) * 1024
                  + SWZ(((o & 7) << 7) | ((K & 31) * 4));
    *(uint32_t*)(g_wt + addr) = t;
}

// ---------------- main kernel ----------------

__global__ __launch_bounds__(NTHREADS, 1)
void conv_mma(const __grid_constant__ CUtensorMap tmap,
              const float* __restrict__ bias, float* __restrict__ out)
{
#if CONV_HAS_TCGEN05
    extern __shared__ __align__(1024) unsigned char sm[];
    const uint32_t smb = smem_u32(sm);
    const int tid = threadIdx.x;
    const int g = blockIdx.x;
    const int wid = tid >> 5, lid = tid & 31;

    const uint32_t mb_full  = smb + SM_MBAR;          // +s*8, s<7
    const uint32_t mb_empty = smb + SM_MBAR + 56;     // +s*8
    const uint32_t mb_tile  = smb + SM_MBAR + 112;
    const uint32_t mb_epi   = smb + SM_MBAR + 120;
    const uint32_t mb_bok   = smb + SM_MBAR + 128;

    if (tid == 0) {
        #pragma unroll
        for (int s = 0; s < NBUF; ++s) {
            MBARRIER_INIT(mb_full + s * 8, 1);
            MBARRIER_INIT(mb_empty + s * 8, 1);
        }
        MBARRIER_INIT(mb_tile, 1);
        MBARRIER_INIT(mb_epi, 4);
        MBARRIER_INIT(mb_bok, 1);
    }
    if (tid < CO) ((float*)(sm + SM_BIAS))[tid] = bias[g * CO + tid];
    if (wid == 0) TCGEN05_ALLOC(smb + SM_TMEMPTR, 512);
    __syncthreads();

    uint32_t tmem;
    asm volatile("ld.shared.b32 %0, [%1];" : "=r"(tmem) : "r"(smb + SM_TMEMPTR));

    if (wid == 5) {
        // ============ TMA warp ============
        if (elect_one()) {
            MBARRIER_EXPECT_TX(mb_bok, B_BYTES);
            BULK_G2S(smb + SM_B, (const void*)(g_wt + (size_t)g * B_BYTES),
                     B_BYTES, mb_bok);
            int ph_e[NBUF] = {0,0,0,0,0,0,0};
            for (int p = 0; p < CHUNKS; ++p) {
                const int s = p % NBUF;
                const int tile = p / 3, i = p % 3;
                const int bb = tile >> 2, t0 = (tile & 3) << 7;
                if (p >= NBUF) {
                    MBARRIER_WAIT_RELAXED(mb_empty + s * 8, ph_e[s]);
                    ph_e[s] ^= 1;
                }
                MBARRIER_EXPECT_TX(mb_full + s * 8, 16384);
                TMA_LOAD_4D(smb + SM_A + s * 16384, &tmap,
                            i * 32, g, t0, bb, mb_full + s * 8);
            }
        }
    } else if (wid == 4) {
        // ============ MMA warp ============
        MBARRIER_WAIT_PARITY(mb_bok, 0);
        if (elect_one()) {
            int ph_f[NBUF] = {0,0,0,0,0,0,0};
            int ph_epi = 0;
            for (int cc = 0; cc < CHUNKS; ++cc) {
                const int s = cc % NBUF;
                const int tile = cc / 3, i = cc % 3;
                MBARRIER_WAIT_RELAXED(mb_full + s * 8, ph_f[s]);
                ph_f[s] ^= 1;
                if (i == 0 && tile >= 1) {
                    MBARRIER_WAIT_RELAXED(mb_epi, ph_epi);
                    ph_epi ^= 1;
                    TCGEN05_FENCE_AFTER();
                }
                const uint64_t ad = make_desc(smb + SM_A + s * 16384);
                #pragma unroll
                for (int stp = 0; stp < 4; ++stp) {
                    const uint32_t en = (i > 0 || stp > 0) ? 1u : 0u;
                    #pragma unroll
                    for (int k = 0; k < 3; ++k) {
                        const uint64_t bd = make_desc(smb + SM_B + (k * 3 + i) * ACOLT);
                        mma_tf32_ss(tmem + (uint32_t)(k * 96),
                                    ad + 2 * stp, bd + 2 * stp, IDESC_T, en);
                    }
                }
                TCGEN05_COMMIT(mb_empty + s * 8);
                if (i == 2) TCGEN05_COMMIT(mb_tile);
            }
        }
    } else {
        // ============ EPILOGUE warps (0..3) ============
        int ph_t = 0;
        const float* bsm = (const float*)(sm + SM_BIAS);
        for (int tile = 0; tile < 16; ++tile) {
            MBARRIER_WAIT_PARITY(mb_tile, ph_t);
            ph_t ^= 1;
            TCGEN05_FENCE_AFTER();
            const int tp = tile & 1;
            const bool firstT = ((tile & 3) == 0);
            const bool lastT  = ((tile & 3) == 3);
            const int bb = tile >> 2, t0 = (tile & 3) << 7;
            const int r = wid * 32 + lid;
            float* oprow  = out + (((size_t)bb * CT + t0 + r) * CG + g) * CO;
            float* opprev = out + (((size_t)bb * CT + (t0 - 1)) * CG + g) * CO;

            #pragma unroll
            for (int cb = 0; cb < 3; ++cb) {
                uint32_t r0[32], r1[32], r2[32];
                TCGEN05_LD_32X32B_X32(r0, tmem + cb * 32);
                TCGEN05_LD_32X32B_X32(r1, tmem + 96 + cb * 32);
                TCGEN05_LD_32X32B_X32(r2, tmem + 192 + cb * 32);
                TCGEN05_WAIT_LD();

                // boundary exchange between warps
                if (lid == 31) {
                    float* d = (float*)(sm + SM_EXG0) + wid * 32;
                    #pragma unroll
                    for (int c = 0; c < 32; ++c) d[c] = __uint_as_float(r0[c]);
                }
                if (lid == 0) {
                    float* d = (float*)(sm + SM_EXG2) + wid * 32;
                    #pragma unroll
                    for (int c = 0; c < 32; ++c) d[c] = __uint_as_float(r2[c]);
                }
                asm volatile("bar.sync 1, 128;" ::: "memory");

                const float* exg0    = (const float*)(sm + SM_EXG0) + (wid - 1) * 32;
                const float* exg2    = (const float*)(sm + SM_EXG2) + (wid + 1) * 32;
                const float* carry_r = (const float*)(sm + SM_CARRY) + (tp ^ 1) * 96 + cb * 32;
                float*       carry_w = (float*)(sm + SM_CARRY) + tp * 96 + cb * 32;
                const float* pend_r  = (const float*)(sm + SM_PEND) + (tp ^ 1) * 96 + cb * 32;
                float*       pend_w  = (float*)(sm + SM_PEND) + tp * 96 + cb * 32;

                float val[32];
                #pragma unroll
                for (int c = 0; c < 32; ++c) {
                    float g0v = __uint_as_float(r0[c]);
                    float g2v = __uint_as_float(r2[c]);
                    float g0p = __shfl_up_sync(0xFFFFFFFFu, g0v, 1);
                    float g2n = __shfl_down_sync(0xFFFFFFFFu, g2v, 1);
                    if (lid == 0)
                        g0p = (wid > 0) ? exg0[c] : (firstT ? 0.f : carry_r[c]);
                    if (lid == 31)
                        g2n = (wid < 3) ? exg2[c] : 0.f;
                    val[c] = g0p + __uint_as_float(r1[c]) + g2n + bsm[cb * 32 + c];
                }

                if (wid == 3 && lid == 31) {
                    // row r=127: save carry; pend unless last tile in batch
                    #pragma unroll
                    for (int c = 0; c < 32; ++c) carry_w[c] = __uint_as_float(r0[c]);
                    if (lastT) {
                        #pragma unroll
                        for (int q = 0; q < 8; ++q)
                            *(float4*)(oprow + cb * 32 + q * 4) =
                                make_float4(val[q*4], val[q*4+1], val[q*4+2], val[q*4+3]);
                    } else {
                        #pragma unroll
                        for (int c = 0; c < 32; ++c) pend_w[c] = val[c];
                    }
                } else {
                    #pragma unroll
                    for (int q = 0; q < 8; ++q)
                        *(float4*)(oprow + cb * 32 + q * 4) =
                            make_float4(val[q*4], val[q*4+1], val[q*4+2], val[q*4+3]);
                }

                // finalize previous tile's row t0-1 with this tile's G2[0]
                if (wid == 0 && lid == 0 && !firstT) {
                    #pragma unroll
                    for (int q = 0; q < 8; ++q) {
                        float4 v;
                        v.x = pend_r[q*4+0] + __uint_as_float(r2[q*4+0]);
                        v.y = pend_r[q*4+1] + __uint_as_float(r2[q*4+1]);
                        v.z = pend_r[q*4+2] + __uint_as_float(r2[q*4+2]);
                        v.w = pend_r[q*4+3] + __uint_as_float(r2[q*4+3]);
                        *(float4*)(opprev + cb * 32 + q * 4) = v;
                    }
                }
                asm volatile("bar.sync 1, 128;" ::: "memory");
            }
            TCGEN05_FENCE_BEFORE();
            __syncwarp();
            if (lid == 0) MBARRIER_ARRIVE(mb_epi);
        }
    }

    __syncthreads();
    if (tid == 0) {
        #pragma unroll
        for (int s = 0; s < NBUF; ++s) {
            MBARRIER_INVAL(mb_full + s * 8);
            MBARRIER_INVAL(mb_empty + s * 8);
        }
        MBARRIER_INVAL(mb_tile);
        MBARRIER_INVAL(mb_epi);
        MBARRIER_INVAL(mb_bok);
    }
    __syncthreads();
    if (wid == 0) TCGEN05_DEALLOC(tmem, 512);
#endif // CONV_HAS_TCGEN05
}

// ---------------- FFMA fallback ----------------

#define TILE_T 128
#define TT (TILE_T + 2)
#define XST (CF + 1)
#define FKc (CF * CK)
#define WST (FKc + 1)
#define FB_SMEM_BYTES ((CO * WST + TT * XST) * 4)

__global__ __launch_bounds__(256, 1)
void conv_fallback(const float* __restrict__ x, const float* __restrict__ w,
                   const float* __restrict__ bias, float* __restrict__ out)
{
    extern __shared__ float sh[];
    float* w_sh = sh;
    float* x_sh = sh + CO * WST;
    const int g  = blockIdx.x;
    const int t0 = blockIdx.y * TILE_T;
    const int b  = blockIdx.z;
    const int tid = threadIdx.x;
    const int tx = tid & 15, ty = tid >> 4;

    {
        const float4* wg = reinterpret_cast<const float4*>(w + (size_t)g * CO * FKc);
        #pragma unroll 4
        for (int idx = tid; idx < CO * FKc / 4; idx += 256) {
            int o = idx / (FKc / 4), c = idx - o * (FKc / 4);
            float4 v = wg[idx];
            float* d = &w_sh[o * WST + c * 4];
            d[0] = v.x; d[1] = v.y; d[2] = v.z; d[3] = v.w;
        }
    }
    {
        #pragma unroll 4
        for (int idx = tid; idx < TT * (CF / 4); idx += 256) {
            int r = idx / (CF / 4), c = idx - r * (CF / 4);
            int t = t0 - 1 + r;
            float4 v = make_float4(0.f, 0.f, 0.f, 0.f);
            if (t >= 0 && t < CT)
                v = reinterpret_cast<const float4*>(
                        x + ((size_t)(b * CT + t) * CG + g) * CF)[c];
            float* d = &x_sh[r * XST + c * 4];
            d[0] = v.x; d[1] = v.y; d[2] = v.z; d[3] = v.w;
        }
    }
    __syncthreads();

    float acc[8][6];
    #pragma unroll
    for (int i = 0; i < 8; i++)
        #pragma unroll
        for (int jj = 0; jj < 6; jj++) acc[i][jj] = 0.f;

    const int obase = tx * 6;
    #pragma unroll
    for (int k = 0; k < CK; k++) {
        const float* xp = &x_sh[(ty + k) * XST];
        const float* wp = &w_sh[obase * WST + k];
        #pragma unroll 2
        for (int f = 0; f < CF; f++) {
            float xr[8];
            #pragma unroll
            for (int i = 0; i < 8; i++) xr[i] = xp[i * 16 * XST + f];
            #pragma unroll
            for (int jj = 0; jj < 6; jj++) {
                float wv = wp[jj * WST + f * 3];
                #pragma unroll
                for (int i = 0; i < 8; i++) acc[i][jj] = fmaf(xr[i], wv, acc[i][jj]);
            }
        }
    }

    const float* bg = bias + g * CO + obase;
    float bv[6];
    #pragma unroll
    for (int jj = 0; jj < 6; jj++) bv[jj] = bg[jj];
    #pragma unroll
    for (int i = 0; i < 8; i++) {
        int t = t0 + ty + i * 16;
        float* op = out + ((size_t)(b * CT + t) * CG + g) * CO + obase;
        #pragma unroll
        for (int jj = 0; jj < 6; jj += 2) {
            float2 v2 = make_float2(acc[i][jj] + bv[jj], acc[i][jj + 1] + bv[jj + 1]);
            *reinterpret_cast<float2*>(op + jj) = v2;
        }
    }
}

// ---------------- launch ----------------

typedef CUresult (*EncodeTiledFn)(
    CUtensorMap*, CUtensorMapDataType, cuuint32_t, void*,
    const cuuint64_t*, const cuuint64_t*, const cuuint32_t*, const cuuint32_t*,
    CUtensorMapInterleave, CUtensorMapSwizzle, CUtensorMapL2promotion,
    CUtensorMapFloatOOBfill);

extern "C" void kernel_launch(void* const* d_in, const int* in_sizes, int n_in,
                              void* d_out, int out_size)
{
    const float* x    = (const float*)d_in[0];
    const float* w    = (const float*)d_in[1];
    const float* bias = (const float*)d_in[2];
    float* out        = (float*)d_out;

    cudaFuncAttributes attr{};
    cudaFuncGetAttributes(&attr, conv_mma);

    static EncodeTiledFn enc_fn = nullptr;
    static bool enc_tried = false;
    if (!enc_tried) {
        enc_tried = true;
        cudaDriverEntryPointQueryResult st;
        void* fn = nullptr;
        if (cudaGetDriverEntryPoint("cuTensorMapEncodeTiled", &fn,
                                    cudaEnableDefault, &st) == cudaSuccess &&
            st == cudaDriverEntryPointSuccess)
            enc_fn = (EncodeTiledFn)fn;
    }

    bool use_mma = (attr.numRegs >= 32) && (enc_fn != nullptr);
    CUtensorMap tmap{};
    if (use_mma) {
        cuuint64_t dims[4]    = {CF, CG, CT, CB};
        cuuint64_t strides[3] = {(cuuint64_t)CF * 4,
                                 (cuuint64_t)CG * CF * 4,
                                 (cuuint64_t)CT * CG * CF * 4};
        cuuint32_t box[4]     = {32, 1, 128, 1};
        cuuint32_t estr[4]    = {1, 1, 1, 1};
        CUresult r = enc_fn(&tmap, CU_TENSOR_MAP_DATA_TYPE_FLOAT32, 4, (void*)x,
                            dims, strides, box, estr,
                            CU_TENSOR_MAP_INTERLEAVE_NONE,
                            CU_TENSOR_MAP_SWIZZLE_128B,
                            CU_TENSOR_MAP_L2_PROMOTION_L2_128B,
                            CU_TENSOR_MAP_FLOAT_OOB_FILL_NONE);
        if (r != CUDA_SUCCESS) use_mma = false;
    }

    if (use_mma) {
        const int ntask = CG * CO * 288;
        prep_w<<<(ntask + 255) / 256, 256>>>(w);
        cudaFuncSetAttribute(conv_mma,
                             cudaFuncAttributeMaxDynamicSharedMemorySize, SMEM_TOTAL);
        conv_mma<<<CG, NTHREADS, SMEM_TOTAL>>>(tmap, bias, out);
    } else {
        cudaFuncSetAttribute(conv_fallback,
                             cudaFuncAttributeMaxDynamicSharedMemorySize, FB_SMEM_BYTES);
        dim3 grid(CG, CT / TILE_T, CB);
        conv_fallback<<<grid, 256, FB_SMEM_BYTES>>>(x, w, bias, out);
    }
}

// round 11
// speedup vs baseline: 1.6800x; 1.6800x over previous
#include <cuda_runtime.h>
#include <cuda.h>
#include <cstdint>

// Conv1dGroup as 129 tf32 tcgen05 GEMMs (sm_103a).
// A (unfolded x, raw fp32 consumed as tf32) staged by 4 LDG->STS copy warps
// into a 7-deep 16KB swizzled ring; 1 MMA warp; 4 epilogue warps with
// double-buffered TMEM accumulators. B pre-rounded tf32 via one bulk copy.
// GEMM per g: D[M=2048 (b,t), N=96 (o)] = A[M, K=288 (k*96+f)] * B[N, K]^T

#define CB 4
#define CT 512
#define CG 129
#define CF 96
#define CO 96
#define CK 3

#define ACOLT 12288                 // B bytes per 32-K atom col
#define NKB 9                       // 9 K blocks (K=288)
#define B_BYTES (NKB * ACOLT)       // 110592
#define NBUF 7
#define CHUNKS (16 * NKB)           // 144
#define NTHREADS 288                // 4 epi + 1 mma + 4 copy warps

#define SWZ(x) ((x) ^ (((x) >> 3) & 0x70))
#define IDESC_T ((1u<<4) | (2u<<7) | (2u<<10) | ((CO/8)<<17) | ((128/16)<<24))

#define SM_B       0
#define SM_A       110592           // 7 x 16384 -> ends 225280
#define SM_BIAS    225280
#define SM_TMEMPTR 225664
#define SM_MBAR    225680
// full[7]@0..55  empty[7]@56..111  tile[2]@112,120  epi[2]@128,136  bok@144
#define SMEM_TOTAL 225920

#if defined(__CUDA_ARCH_FEAT_SM103_ALL) || defined(__CUDA_ARCH_FEAT_SM100_ALL)
#define CONV_HAS_TCGEN05 1
#else
#define CONV_HAS_TCGEN05 0
#endif

__device__ __align__(16) unsigned char g_wt[CG * B_BYTES];

static __device__ __forceinline__ uint32_t smem_u32(const void* p) {
    uint32_t a;
    asm("{ .reg .u64 t; cvta.to.shared.u64 t, %1; cvt.u32.u64 %0, t; }" : "=r"(a) : "l"(p));
    return a;
}

#define MBARRIER_INIT(addr, cnt) \
    asm volatile("mbarrier.init.shared.b64 [%0], %1;" :: "r"(addr), "r"(cnt) : "memory")
#define MBARRIER_INVAL(addr) \
    asm volatile("mbarrier.inval.shared.b64 [%0];" :: "r"(addr) : "memory")
#define MBARRIER_ARRIVE(addr) \
    asm volatile("mbarrier.arrive.shared.b64 _, [%0];" :: "r"((uint32_t)(addr)) : "memory")
#define MBARRIER_EXPECT_TX(addr, bytes) \
    asm volatile("mbarrier.arrive.expect_tx.shared.b64 _, [%0], %1;" \
                 :: "r"((uint32_t)(addr)), "r"((uint32_t)(bytes)) : "memory")
#define MBARRIER_WAIT_PARITY(addr, parity) do {                                    \
    asm volatile(                                                                  \
        "{\n\t.reg .pred P;\n\t"                                                   \
        "WL_%=:\n\t"                                                               \
        "mbarrier.try_wait.parity.acquire.cta.shared::cta.b64 P, [%0], %1, 0x989680;\n\t" \
        "@P bra.uni WD_%=;\n\t"                                                    \
        "bra.uni WL_%=;\n\t"                                                       \
        "WD_%=:\n\t}"                                                              \
        :: "r"((uint32_t)(addr)), "r"((uint32_t)(parity)) : "memory");             \
} while (0)
#define FENCE_PROXY_ASYNC() asm volatile("fence.proxy.async.shared::cta;" ::: "memory")

#if CONV_HAS_TCGEN05

#define TCGEN05_ALLOC(smaddr, ncols) \
    asm volatile("tcgen05.alloc.cta_group::1.sync.aligned.shared::cta.b32 [%0], %1;" \
                 :: "r"((uint32_t)(smaddr)), "r"((uint32_t)(ncols)) : "memory")
#define TCGEN05_DEALLOC(tm, ncols) \
    asm volatile("tcgen05.dealloc.cta_group::1.sync.aligned.b32 %0, %1;" \
                 :: "r"(tm), "r"((uint32_t)(ncols)))
#define TCGEN05_COMMIT(mbar) \
    asm volatile("tcgen05.commit.cta_group::1.mbarrier::arrive::one.shared::cluster.b64 [%0];" \
                 :: "r"((uint32_t)(mbar)) : "memory")
#define TCGEN05_WAIT_LD() asm volatile("tcgen05.wait::ld.sync.aligned;" ::: "memory")
#define TCGEN05_FENCE_BEFORE() asm volatile("tcgen05.fence::before_thread_sync;" ::: "memory")
#define TCGEN05_FENCE_AFTER()  asm volatile("tcgen05.fence::after_thread_sync;" ::: "memory")

#define TCGEN05_LD_32X32B_X32(r, tmaddr) \
    asm volatile( \
        "tcgen05.ld.sync.aligned.32x32b.x32.b32 " \
        "{%0, %1, %2, %3, %4, %5, %6, %7, " \
        " %8, %9, %10, %11, %12, %13, %14, %15, " \
        " %16, %17, %18, %19, %20, %21, %22, %23, " \
        " %24, %25, %26, %27, %28, %29, %30, %31}, [%32];" \
        : "=r"((r)[0]),  "=r"((r)[1]),  "=r"((r)[2]),  "=r"((r)[3]), \
          "=r"((r)[4]),  "=r"((r)[5]),  "=r"((r)[6]),  "=r"((r)[7]), \
          "=r"((r)[8]),  "=r"((r)[9]),  "=r"((r)[10]), "=r"((r)[11]), \
          "=r"((r)[12]), "=r"((r)[13]), "=r"((r)[14]), "=r"((r)[15]), \
          "=r"((r)[16]), "=r"((r)[17]), "=r"((r)[18]), "=r"((r)[19]), \
          "=r"((r)[20]), "=r"((r)[21]), "=r"((r)[22]), "=r"((r)[23]), \
          "=r"((r)[24]), "=r"((r)[25]), "=r"((r)[26]), "=r"((r)[27]), \
          "=r"((r)[28]), "=r"((r)[29]), "=r"((r)[30]), "=r"((r)[31]) \
        : "r"(tmaddr))

#define BULK_G2S(smaddr, gptr, bytes, mbar) \
    asm volatile( \
        "cp.async.bulk.shared::cta.global.mbarrier::complete_tx::bytes [%0], [%1], %2, [%3];" \
        :: "r"((uint32_t)(smaddr)), "l"(gptr), "r"((uint32_t)(bytes)), \
           "r"((uint32_t)(mbar)) : "memory")

static constexpr uint64_t SMEM_DESC_BASE_SW128 =
    (uint64_t(2) << 61) | (uint64_t(1) << 46) | (uint64_t(64) << 32) | (uint64_t(1) << 16);

static __device__ __forceinline__ uint64_t make_desc(uint32_t smaddr) {
    return SMEM_DESC_BASE_SW128 | ((uint64_t)(smaddr >> 4) & 0x3FFF);
}

static __device__ __forceinline__ void mma_tf32_ss(uint32_t d, uint64_t a, uint64_t b,
                                                   uint32_t idesc, uint32_t en) {
    asm volatile(
        "{\n\t.reg .pred p;\n\t"
        "setp.ne.u32 p, %4, 0;\n\t"
        "tcgen05.mma.cta_group::1.kind::tf32 [%0], %1, %2, %3, p;\n\t}"
        :: "r"(d), "l"(a), "l"(b), "r"(idesc), "r"(en) : "memory");
}

static __device__ __forceinline__ uint32_t elect_one() {
    uint32_t pred;
    asm volatile(
        "{\n\t.reg .pred p;\n\t"
        "elect.sync _|p, 0xFFFFFFFF;\n\t"
        "selp.b32 %0, 1, 0, p;\n\t}" : "=r"(pred));
    return pred;
}

#endif // CONV_HAS_TCGEN05

// -------- pre-kernel: weights -> tf32 (rna) in MMA SMEM layout --------

__global__ __launch_bounds__(256) void prep_w(const float* __restrict__ w) {
    int id = blockIdx.x * 256 + threadIdx.x;
    const int NTASK = CG * CO * 288;
    if (id >= NTASK) return;
    int K = id % 288;
    int o = (id / 288) % CO;
    int g = id / (288 * CO);
    int k = K / CF, f = K - CF * k;
    float v = w[(((size_t)(g * CO + o) * CF + f) * CK + k)];
    uint32_t t;
    asm("cvt.rna.tf32.f32 %0, %1;" : "=r"(t) : "f"(v));
    uint32_t addr = (uint32_t)g * B_BYTES + (K >> 5) * ACOLT + (o >> 3) * 1024
                  + SWZ(((o & 7) << 7) | ((K & 31) * 4));
    *(uint32_t*)(g_wt + addr) = t;
}

// ---------------- main kernel ----------------

__global__ __launch_bounds__(NTHREADS, 1)
void conv_mma(const float* __restrict__ x,
              const float* __restrict__ bias, float* __restrict__ out)
{
#if CONV_HAS_TCGEN05
    extern __shared__ __align__(1024) unsigned char sm[];
    const uint32_t smb = smem_u32(sm);
    const int tid = threadIdx.x;
    const int g = blockIdx.x;
    const int wid = tid >> 5, lid = tid & 31;

    const uint32_t mb_full  = smb + SM_MBAR;          // +s*8, s<7
    const uint32_t mb_empty = smb + SM_MBAR + 56;     // +s*8
    const uint32_t mb_tile  = smb + SM_MBAR + 112;    // +slot*8
    const uint32_t mb_epi   = smb + SM_MBAR + 128;    // +slot*8
    const uint32_t mb_bok   = smb + SM_MBAR + 144;

    if (tid == 0) {
        #pragma unroll
        for (int s = 0; s < NBUF; ++s) {
            MBARRIER_INIT(mb_full + s * 8, 1);
            MBARRIER_INIT(mb_empty + s * 8, 1);
        }
        MBARRIER_INIT(mb_tile + 0, 1);
        MBARRIER_INIT(mb_tile + 8, 1);
        MBARRIER_INIT(mb_epi + 0, 4);
        MBARRIER_INIT(mb_epi + 8, 4);
        MBARRIER_INIT(mb_bok, 1);
    }
    if (tid < CO) ((float*)(sm + SM_BIAS))[tid] = bias[g * CO + tid];
    if (wid == 0) TCGEN05_ALLOC(smb + SM_TMEMPTR, 256);
    __syncthreads();

    uint32_t tmem;
    asm volatile("ld.shared.b32 %0, [%1];" : "=r"(tmem) : "r"(smb + SM_TMEMPTR));

    if (wid >= 5) {
        // ============ COPY warps (5..8): A ingest, LDG.128 -> swizzled STS ============
        const int cw = wid - 5;                         // 0..3
        const size_t rowstride = (size_t)CG * CF;       // floats per t row
        for (int p = cw; p < CHUNKS; p += 4) {
            const int s = p % NBUF;
            const int tile = p / NKB, kb = p % NKB;
            const int bb = tile >> 2;
            const int t0k = ((tile & 3) << 7) - 1 + (kb / 3);
            const int f0 = (kb % 3) * 32;
            if (p >= NBUF)
                MBARRIER_WAIT_PARITY(mb_empty + s * 8, ((p / NBUF) - 1) & 1);

            const float* rb = x + ((size_t)bb * CT + t0k) * rowstride
                                + (size_t)g * CF + f0;
            unsigned char* ab = sm + SM_A + s * 16384;

            float4 buf[2][8];
            #pragma unroll
            for (int i2 = 0; i2 < 8; ++i2) {
                int id = i2 * 32 + lid;
                int row = id >> 3, seg = id & 7;
                bool ok = (unsigned)(t0k + row) < CT;
                buf[0][i2] = ok ? *(const float4*)(rb + (size_t)row * rowstride + seg * 4)
                                : make_float4(0.f, 0.f, 0.f, 0.f);
            }
            #pragma unroll
            for (int j = 0; j < 4; ++j) {
                if (j < 3) {
                    #pragma unroll
                    for (int i2 = 0; i2 < 8; ++i2) {
                        int id = ((j + 1) * 8 + i2) * 32 + lid;
                        int row = id >> 3, seg = id & 7;
                        bool ok = (unsigned)(t0k + row) < CT;
                        buf[(j + 1) & 1][i2] =
                            ok ? *(const float4*)(rb + (size_t)row * rowstride + seg * 4)
                               : make_float4(0.f, 0.f, 0.f, 0.f);
                    }
                }
                #pragma unroll
                for (int i2 = 0; i2 < 8; ++i2) {
                    int id = (j * 8 + i2) * 32 + lid;
                    int row = id >> 3, seg = id & 7;
                    uint32_t off = ((uint32_t)(row >> 3) << 10)
                                 + SWZ((uint32_t)(((row & 7) << 7) | (seg << 4)));
                    *(float4*)(ab + off) = buf[j & 1][i2];
                }
            }
            FENCE_PROXY_ASYNC();
            __syncwarp();
            if (lid == 0) MBARRIER_ARRIVE(mb_full + s * 8);
        }
    } else if (wid == 4) {
        // ============ MMA warp ============
        if (elect_one()) {
            MBARRIER_EXPECT_TX(mb_bok, B_BYTES);
            BULK_G2S(smb + SM_B, (const void*)(g_wt + (size_t)g * B_BYTES),
                     B_BYTES, mb_bok);
        }
        MBARRIER_WAIT_PARITY(mb_bok, 0);
        if (elect_one()) {
            int ph_f[NBUF] = {0,0,0,0,0,0,0};
            int ph_epi[2] = {0, 0};
            for (int cc = 0; cc < CHUNKS; ++cc) {
                const int s = cc % NBUF;
                const int tile = cc / NKB, kb = cc % NKB;
                const int slot = tile & 1;
                const uint32_t dslot = tmem + (uint32_t)(slot * 128);
                MBARRIER_WAIT_PARITY(mb_full + s * 8, ph_f[s]);
                ph_f[s] ^= 1;
                if (kb == 0 && tile >= 2) {
                    MBARRIER_WAIT_PARITY(mb_epi + slot * 8, ph_epi[slot]);
                    ph_epi[slot] ^= 1;
                    TCGEN05_FENCE_AFTER();
                }
                const uint64_t ad = make_desc(smb + SM_A + s * 16384);
                const uint64_t bd = make_desc(smb + SM_B + kb * ACOLT);
                #pragma unroll
                for (int stp = 0; stp < 4; ++stp) {
                    uint32_t en = (kb > 0 || stp > 0) ? 1u : 0u;
                    mma_tf32_ss(dslot, ad + 2 * stp, bd + 2 * stp, IDESC_T, en);
                }
                TCGEN05_COMMIT(mb_empty + s * 8);
                if (kb == NKB - 1) TCGEN05_COMMIT(mb_tile + slot * 8);
            }
        }
    } else {
        // ============ EPILOGUE warps (0..3) ============
        const int sub = wid;
        int ph_t[2] = {0, 0};
        const float* bsm = (const float*)(sm + SM_BIAS);
        for (int tile = 0; tile < 16; ++tile) {
            const int slot = tile & 1;
            MBARRIER_WAIT_PARITY(mb_tile + slot * 8, ph_t[slot]);
            ph_t[slot] ^= 1;
            TCGEN05_FENCE_AFTER();
            const int trow = (tile & 3) * 128 + sub * 32 + lid;
            const int bb = tile >> 2;
            float* op = out + (((size_t)bb * CT + trow) * CG + g) * CO;
            const uint32_t D = tmem + (uint32_t)(slot * 128);
            #pragma unroll
            for (int bch = 0; bch < 3; ++bch) {
                uint32_t r[32];
                TCGEN05_LD_32X32B_X32(r, D + bch * 32);
                TCGEN05_WAIT_LD();
                #pragma unroll
                for (int q4 = 0; q4 < 8; ++q4) {
                    float4 bv = *(const float4*)(bsm + bch * 32 + q4 * 4);
                    float4 v;
                    v.x = __uint_as_float(r[q4 * 4 + 0]) + bv.x;
                    v.y = __uint_as_float(r[q4 * 4 + 1]) + bv.y;
                    v.z = __uint_as_float(r[q4 * 4 + 2]) + bv.z;
                    v.w = __uint_as_float(r[q4 * 4 + 3]) + bv.w;
                    *(float4*)(op + bch * 32 + q4 * 4) = v;
                }
            }
            TCGEN05_FENCE_BEFORE();
            __syncwarp();
            if (lid == 0) MBARRIER_ARRIVE(mb_epi + slot * 8);
        }
    }

    __syncthreads();
    if (tid == 0) {
        #pragma unroll
        for (int s = 0; s < NBUF; ++s) {
            MBARRIER_INVAL(mb_full + s * 8);
            MBARRIER_INVAL(mb_empty + s * 8);
        }
        MBARRIER_INVAL(mb_tile + 0); MBARRIER_INVAL(mb_tile + 8);
        MBARRIER_INVAL(mb_epi + 0);  MBARRIER_INVAL(mb_epi + 8);
        MBARRIER_INVAL(mb_bok);
    }
    __syncthreads();
    if (wid == 0) TCGEN05_DEALLOC(tmem, 256);
#endif // CONV_HAS_TCGEN05
}

// ---------------- FFMA fallback ----------------

#define TILE_T 128
#define TT (TILE_T + 2)
#define XST (CF + 1)
#define FKc (CF * CK)
#define WST (FKc + 1)
#define FB_SMEM_BYTES ((CO * WST + TT * XST) * 4)

__global__ __launch_bounds__(256, 1)
void conv_fallback(const float* __restrict__ x, const float* __restrict__ w,
                   const float* __restrict__ bias, float* __restrict__ out)
{
    extern __shared__ float sh[];
    float* w_sh = sh;
    float* x_sh = sh + CO * WST;
    const int g  = blockIdx.x;
    const int t0 = blockIdx.y * TILE_T;
    const int b  = blockIdx.z;
    const int tid = threadIdx.x;
    const int tx = tid & 15, ty = tid >> 4;

    {
        const float4* wg = reinterpret_cast<const float4*>(w + (size_t)g * CO * FKc);
        #pragma unroll 4
        for (int idx = tid; idx < CO * FKc / 4; idx += 256) {
            int o = idx / (FKc / 4), c = idx - o * (FKc / 4);
            float4 v = wg[idx];
            float* d = &w_sh[o * WST + c * 4];
            d[0] = v.x; d[1] = v.y; d[2] = v.z; d[3] = v.w;
        }
    }
    {
        #pragma unroll 4
        for (int idx = tid; idx < TT * (CF / 4); idx += 256) {
            int r = idx / (CF / 4), c = idx - r * (CF / 4);
            int t = t0 - 1 + r;
            float4 v = make_float4(0.f, 0.f, 0.f, 0.f);
            if (t >= 0 && t < CT)
                v = reinterpret_cast<const float4*>(
                        x + ((size_t)(b * CT + t) * CG + g) * CF)[c];
            float* d = &x_sh[r * XST + c * 4];
            d[0] = v.x; d[1] = v.y; d[2] = v.z; d[3] = v.w;
        }
    }
    __syncthreads();

    float acc[8][6];
    #pragma unroll
    for (int i = 0; i < 8; i++)
        #pragma unroll
        for (int jj = 0; jj < 6; jj++) acc[i][jj] = 0.f;

    const int obase = tx * 6;
    #pragma unroll
    for (int k = 0; k < CK; k++) {
        const float* xp = &x_sh[(ty + k) * XST];
        const float* wp = &w_sh[obase * WST + k];
        #pragma unroll 2
        for (int f = 0; f < CF; f++) {
            float xr[8];
            #pragma unroll
            for (int i = 0; i < 8; i++) xr[i] = xp[i * 16 * XST + f];
            #pragma unroll
            for (int jj = 0; jj < 6; jj++) {
                float wv = wp[jj * WST + f * 3];
                #pragma unroll
                for (int i = 0; i < 8; i++) acc[i][jj] = fmaf(xr[i], wv, acc[i][jj]);
            }
        }
    }

    const float* bg = bias + g * CO + obase;
    float bv[6];
    #pragma unroll
    for (int jj = 0; jj < 6; jj++) bv[jj] = bg[jj];
    #pragma unroll
    for (int i = 0; i < 8; i++) {
        int t = t0 + ty + i * 16;
        float* op = out + ((size_t)(b * CT + t) * CG + g) * CO + obase;
        #pragma unroll
        for (int jj = 0; jj < 6; jj += 2) {
            float2 v2 = make_float2(acc[i][jj] + bv[jj], acc[i][jj + 1] + bv[jj + 1]);
            *reinterpret_cast<float2*>(op + jj) = v2;
        }
    }
}

// ---------------- launch ----------------

extern "C" void kernel_launch(void* const* d_in, const int* in_sizes, int n_in,
                              void* d_out, int out_size)
{
    const float* x    = (const float*)d_in[0];
    const float* w    = (const float*)d_in[1];
    const float* bias = (const float*)d_in[2];
    float* out        = (float*)d_out;

    cudaFuncAttributes attr{};
    cudaFuncGetAttributes(&attr, conv_mma);

    if (attr.numRegs >= 32) {
        const int ntask = CG * CO * 288;
        prep_w<<<(ntask + 255) / 256, 256>>>(w);
        cudaFuncSetAttribute(conv_mma,
                             cudaFuncAttributeMaxDynamicSharedMemorySize, SMEM_TOTAL);
        conv_mma<<<CG, NTHREADS, SMEM_TOTAL>>>(x, bias, out);
    } else {
        cudaFuncSetAttribute(conv_fallback,
                             cudaFuncAttributeMaxDynamicSharedMemorySize, FB_SMEM_BYTES);
        dim3 grid(CG, CT / TILE_T, CB);
        conv_fallback<<<grid, 256, FB_SMEM_BYTES>>>(x, w, bias, out);
    }
}

// round 12
// speedup vs baseline: 1.9221x; 1.1441x over previous
#include <cuda_runtime.h>
#include <cuda.h>
#include <cstdint>

// Conv1dGroup as 129 tf32 tcgen05 GEMMs. A fed by TMA (unfold via shifted 4D
// coords, OOB zero), each 16KB chunk split into 4 concurrent 32-row TMA ops
// for row-level parallelism. 1 TMA warp + 1 MMA warp + 4 epilogue warps;
// 7-deep 16KB A ring. FFMA fallback for non-'a' passes.

#define CB 4
#define CT 512
#define CG 129
#define CF 96
#define CO 96
#define CK 3

#define ACOLT 12288                 // B bytes per 32-K atom col
#define NKB 9                       // 9 used K blocks (K=288)
#define B_BYTES (NKB * ACOLT)       // 110592
#define NBUF 7
#define CHUNKS (16 * NKB)           // 144
#define NTHREADS 192                // 4 epi + 1 mma + 1 tma

#define SWZ(x) ((x) ^ (((x) >> 3) & 0x70))
#define IDESC_T ((1u<<4) | (2u<<7) | (2u<<10) | ((CO/8)<<17) | ((128/16)<<24))

#define SM_B       0
#define SM_A       110592           // 7 x 16384 -> ends 225280
#define SM_BIAS    225280
#define SM_TMEMPTR 225664
#define SM_MBAR    225680
// full[7]@0..55  empty[7]@56..111  tile[2]@112,120  epi[2]@128,136  bok@144
#define SMEM_TOTAL 225920

#if defined(__CUDA_ARCH_FEAT_SM103_ALL) || defined(__CUDA_ARCH_FEAT_SM100_ALL)
#define CONV_HAS_TCGEN05 1
#else
#define CONV_HAS_TCGEN05 0
#endif

__device__ __align__(16) unsigned char g_wt[CG * B_BYTES];

static __device__ __forceinline__ uint32_t smem_u32(const void* p) {
    uint32_t a;
    asm("{ .reg .u64 t; cvta.to.shared.u64 t, %1; cvt.u32.u64 %0, t; }" : "=r"(a) : "l"(p));
    return a;
}

#define MBARRIER_INIT(addr, cnt) \
    asm volatile("mbarrier.init.shared.b64 [%0], %1;" :: "r"(addr), "r"(cnt) : "memory")
#define MBARRIER_INVAL(addr) \
    asm volatile("mbarrier.inval.shared.b64 [%0];" :: "r"(addr) : "memory")
#define MBARRIER_ARRIVE(addr) \
    asm volatile("mbarrier.arrive.shared.b64 _, [%0];" :: "r"((uint32_t)(addr)) : "memory")
#define MBARRIER_EXPECT_TX(addr, bytes) \
    asm volatile("mbarrier.arrive.expect_tx.shared.b64 _, [%0], %1;" \
                 :: "r"((uint32_t)(addr)), "r"((uint32_t)(bytes)) : "memory")
#define MBAR_WAIT(addr, parity, SEM) do {                                          \
    asm volatile(                                                                  \
        "{\n\t.reg .pred P;\n\t"                                                   \
        "WL_%=:\n\t"                                                               \
        "mbarrier.try_wait.parity." SEM ".cta.shared::cta.b64 P, [%0], %1, 0x989680;\n\t" \
        "@P bra.uni WD_%=;\n\t"                                                    \
        "bra.uni WL_%=;\n\t"                                                       \
        "WD_%=:\n\t}"                                                              \
        :: "r"((uint32_t)(addr)), "r"((uint32_t)(parity)) : "memory");             \
} while (0)
#define MBARRIER_WAIT_PARITY(a, p)  MBAR_WAIT(a, p, "acquire")
#define MBARRIER_WAIT_RELAXED(a, p) MBAR_WAIT(a, p, "relaxed")

#if CONV_HAS_TCGEN05

#define TCGEN05_ALLOC(smaddr, ncols) \
    asm volatile("tcgen05.alloc.cta_group::1.sync.aligned.shared::cta.b32 [%0], %1;" \
                 :: "r"((uint32_t)(smaddr)), "r"((uint32_t)(ncols)) : "memory")
#define TCGEN05_DEALLOC(tm, ncols) \
    asm volatile("tcgen05.dealloc.cta_group::1.sync.aligned.b32 %0, %1;" \
                 :: "r"(tm), "r"((uint32_t)(ncols)))
#define TCGEN05_COMMIT(mbar) \
    asm volatile("tcgen05.commit.cta_group::1.mbarrier::arrive::one.shared::cluster.b64 [%0];" \
                 :: "r"((uint32_t)(mbar)) : "memory")
#define TCGEN05_WAIT_LD() asm volatile("tcgen05.wait::ld.sync.aligned;" ::: "memory")
#define TCGEN05_FENCE_BEFORE() asm volatile("tcgen05.fence::before_thread_sync;" ::: "memory")
#define TCGEN05_FENCE_AFTER()  asm volatile("tcgen05.fence::after_thread_sync;" ::: "memory")

#define TCGEN05_LD_32X32B_X32(r, tmaddr) \
    asm volatile( \
        "tcgen05.ld.sync.aligned.32x32b.x32.b32 " \
        "{%0, %1, %2, %3, %4, %5, %6, %7, " \
        " %8, %9, %10, %11, %12, %13, %14, %15, " \
        " %16, %17, %18, %19, %20, %21, %22, %23, " \
        " %24, %25, %26, %27, %28, %29, %30, %31}, [%32];" \
        : "=r"((r)[0]),  "=r"((r)[1]),  "=r"((r)[2]),  "=r"((r)[3]), \
          "=r"((r)[4]),  "=r"((r)[5]),  "=r"((r)[6]),  "=r"((r)[7]), \
          "=r"((r)[8]),  "=r"((r)[9]),  "=r"((r)[10]), "=r"((r)[11]), \
          "=r"((r)[12]), "=r"((r)[13]), "=r"((r)[14]), "=r"((r)[15]), \
          "=r"((r)[16]), "=r"((r)[17]), "=r"((r)[18]), "=r"((r)[19]), \
          "=r"((r)[20]), "=r"((r)[21]), "=r"((r)[22]), "=r"((r)[23]), \
          "=r"((r)[24]), "=r"((r)[25]), "=r"((r)[26]), "=r"((r)[27]), \
          "=r"((r)[28]), "=r"((r)[29]), "=r"((r)[30]), "=r"((r)[31]) \
        : "r"(tmaddr))

#define TMA_LOAD_4D(smaddr, tmap, c0, c1, c2, c3, mbar) \
    asm volatile( \
        "cp.async.bulk.tensor.4d.shared::cta.global.tile.mbarrier::complete_tx::bytes " \
        "[%0], [%1, {%2, %3, %4, %5}], [%6];" \
        :: "r"((uint32_t)(smaddr)), "l"(tmap), "r"((int)(c0)), "r"((int)(c1)), \
           "r"((int)(c2)), "r"((int)(c3)), "r"((uint32_t)(mbar)) : "memory")

#define BULK_G2S(smaddr, gptr, bytes, mbar) \
    asm volatile( \
        "cp.async.bulk.shared::cta.global.mbarrier::complete_tx::bytes [%0], [%1], %2, [%3];" \
        :: "r"((uint32_t)(smaddr)), "l"(gptr), "r"((uint32_t)(bytes)), \
           "r"((uint32_t)(mbar)) : "memory")

static constexpr uint64_t SMEM_DESC_BASE_SW128 =
    (uint64_t(2) << 61) | (uint64_t(1) << 46) | (uint64_t(64) << 32) | (uint64_t(1) << 16);

static __device__ __forceinline__ uint64_t make_desc(uint32_t smaddr) {
    return SMEM_DESC_BASE_SW128 | ((uint64_t)(smaddr >> 4) & 0x3FFF);
}

static __device__ __forceinline__ void mma_tf32_ss(uint32_t d, uint64_t a, uint64_t b,
                                                   uint32_t idesc, uint32_t en) {
    asm volatile(
        "{\n\t.reg .pred p;\n\t"
        "setp.ne.u32 p, %4, 0;\n\t"
        "tcgen05.mma.cta_group::1.kind::tf32 [%0], %1, %2, %3, p;\n\t}"
        :: "r"(d), "l"(a), "l"(b), "r"(idesc), "r"(en) : "memory");
}

static __device__ __forceinline__ uint32_t elect_one() {
    uint32_t pred;
    asm volatile(
        "{\n\t.reg .pred p;\n\t"
        "elect.sync _|p, 0xFFFFFFFF;\n\t"
        "selp.b32 %0, 1, 0, p;\n\t}" : "=r"(pred));
    return pred;
}

#endif // CONV_HAS_TCGEN05

// -------- pre-kernel: weights -> tf32 (rna) in MMA SMEM layout --------

__global__ __launch_bounds__(256) void prep_w(const float* __restrict__ w) {
    int id = blockIdx.x * 256 + threadIdx.x;
    const int NTASK = CG * CO * 288;
    if (id >= NTASK) return;
    int K = id % 288;
    int o = (id / 288) % CO;
    int g = id / (288 * CO);
    int k = K / CF, f = K - CF * k;
    float v = w[(((size_t)(g * CO + o) * CF + f) * CK + k)];
    uint32_t t;
    asm("cvt.rna.tf32.f32 %0, %1;" : "=r"(t) : "f"(v));
    uint32_t addr = (uint32_t)g * B_BYTES + (K >> 5) * ACOLT + (o >> 3) * 1024
                  + SWZ(((o & 7) << 7) | ((K & 31) * 4));
    *(uint32_t*)(g_wt + addr) = t;
}

// ---------------- main kernel ----------------

__global__ __launch_bounds__(NTHREADS, 1)
void conv_mma(const __grid_constant__ CUtensorMap tmap,
              const float* __restrict__ bias, float* __restrict__ out)
{
#if CONV_HAS_TCGEN05
    extern __shared__ __align__(1024) unsigned char sm[];
    const uint32_t smb = smem_u32(sm);
    const int tid = threadIdx.x;
    const int g = blockIdx.x;
    const int wid = tid >> 5, lid = tid & 31;

    const uint32_t mb_full  = smb + SM_MBAR;          // +s*8, s<7
    const uint32_t mb_empty = smb + SM_MBAR + 56;     // +s*8
    const uint32_t mb_tile  = smb + SM_MBAR + 112;    // +slot*8
    const uint32_t mb_epi   = smb + SM_MBAR + 128;    // +slot*8
    const uint32_t mb_bok   = smb + SM_MBAR + 144;

    if (tid == 0) {
        #pragma unroll
        for (int s = 0; s < NBUF; ++s) {
            MBARRIER_INIT(mb_full + s * 8, 1);
            MBARRIER_INIT(mb_empty + s * 8, 1);
        }
        MBARRIER_INIT(mb_tile + 0, 1);
        MBARRIER_INIT(mb_tile + 8, 1);
        MBARRIER_INIT(mb_epi + 0, 4);
        MBARRIER_INIT(mb_epi + 8, 4);
        MBARRIER_INIT(mb_bok, 1);
    }
    if (tid < CO) ((float*)(sm + SM_BIAS))[tid] = bias[g * CO + tid];
    if (wid == 0) TCGEN05_ALLOC(smb + SM_TMEMPTR, 256);
    __syncthreads();

    uint32_t tmem;
    asm volatile("ld.shared.b32 %0, [%1];" : "=r"(tmem) : "r"(smb + SM_TMEMPTR));

    if (wid == 5) {
        // ============ TMA warp ============
        if (elect_one()) {
            MBARRIER_EXPECT_TX(mb_bok, B_BYTES);
            BULK_G2S(smb + SM_B, (const void*)(g_wt + (size_t)g * B_BYTES),
                     B_BYTES, mb_bok);
            int ph_e[NBUF] = {0,0,0,0,0,0,0};
            for (int p = 0; p < CHUNKS; ++p) {
                const int s = p % NBUF;
                const int tile = p / NKB, kb = p % NKB;
                const int bb = tile >> 2, t0 = (tile & 3) << 7;
                const int k = kb / 3, f0 = (kb % 3) * 32;
                if (p >= NBUF) {
                    MBARRIER_WAIT_RELAXED(mb_empty + s * 8, ph_e[s]);
                    ph_e[s] ^= 1;
                }
                MBARRIER_EXPECT_TX(mb_full + s * 8, 16384);
                // 4 concurrent 32-row sub-loads -> row-level parallelism in
                // the TMA engine. Sub-box images are byte-identical to the
                // corresponding slices of a single 128-row box (32 % 8 == 0).
                #pragma unroll
                for (int q = 0; q < 4; ++q) {
                    TMA_LOAD_4D(smb + SM_A + s * 16384 + q * 4096, &tmap,
                                f0, g, t0 - 1 + k + q * 32, bb, mb_full + s * 8);
                }
            }
        }
    } else if (wid == 4) {
        // ============ MMA warp ============
        MBARRIER_WAIT_PARITY(mb_bok, 0);
        if (elect_one()) {
            int ph_f[NBUF] = {0,0,0,0,0,0,0};
            int ph_epi[2] = {0, 0};
            for (int cc = 0; cc < CHUNKS; ++cc) {
                const int s = cc % NBUF;
                const int tile = cc / NKB, kb = cc % NKB;
                const int slot = tile & 1;
                const uint32_t dslot = tmem + (uint32_t)(slot * 128);
                MBARRIER_WAIT_RELAXED(mb_full + s * 8, ph_f[s]);
                ph_f[s] ^= 1;
                if (kb == 0 && tile >= 2) {
                    MBARRIER_WAIT_RELAXED(mb_epi + slot * 8, ph_epi[slot]);
                    ph_epi[slot] ^= 1;
                }
                const uint64_t ad = make_desc(smb + SM_A + s * 16384);
                const uint64_t bd = make_desc(smb + SM_B + kb * ACOLT);
                #pragma unroll
                for (int stp = 0; stp < 4; ++stp) {
                    uint32_t en = (kb > 0 || stp > 0) ? 1u : 0u;
                    mma_tf32_ss(dslot, ad + 2 * stp, bd + 2 * stp, IDESC_T, en);
                }
                TCGEN05_COMMIT(mb_empty + s * 8);
                if (kb == NKB - 1) TCGEN05_COMMIT(mb_tile + slot * 8);
            }
        }
    } else {
        // ============ EPILOGUE warps (0..3) ============
        const int sub = wid;
        int ph_t[2] = {0, 0};
        const float* bsm = (const float*)(sm + SM_BIAS);
        for (int tile = 0; tile < 16; ++tile) {
            const int slot = tile & 1;
            MBARRIER_WAIT_PARITY(mb_tile + slot * 8, ph_t[slot]);
            ph_t[slot] ^= 1;
            TCGEN05_FENCE_AFTER();
            const int trow = (tile & 3) * 128 + sub * 32 + lid;
            const int bb = tile >> 2;
            float* op = out + (((size_t)bb * CT + trow) * CG + g) * CO;
            const uint32_t D = tmem + (uint32_t)(slot * 128);
            #pragma unroll
            for (int bch = 0; bch < 3; ++bch) {
                uint32_t r[32];
                TCGEN05_LD_32X32B_X32(r, D + bch * 32);
                TCGEN05_WAIT_LD();
                #pragma unroll
                for (int q4 = 0; q4 < 8; ++q4) {
                    float4 bv = *(const float4*)(bsm + bch * 32 + q4 * 4);
                    float4 v;
                    v.x = __uint_as_float(r[q4 * 4 + 0]) + bv.x;
                    v.y = __uint_as_float(r[q4 * 4 + 1]) + bv.y;
                    v.z = __uint_as_float(r[q4 * 4 + 2]) + bv.z;
                    v.w = __uint_as_float(r[q4 * 4 + 3]) + bv.w;
                    *(float4*)(op + bch * 32 + q4 * 4) = v;
                }
            }
            TCGEN05_FENCE_BEFORE();
            __syncwarp();
            if (lid == 0) MBARRIER_ARRIVE(mb_epi + slot * 8);
        }
    }

    __syncthreads();
    if (tid == 0) {
        #pragma unroll
        for (int s = 0; s < NBUF; ++s) {
            MBARRIER_INVAL(mb_full + s * 8);
            MBARRIER_INVAL(mb_empty + s * 8);
        }
        MBARRIER_INVAL(mb_tile + 0); MBARRIER_INVAL(mb_tile + 8);
        MBARRIER_INVAL(mb_epi + 0);  MBARRIER_INVAL(mb_epi + 8);
        MBARRIER_INVAL(mb_bok);
    }
    __syncthreads();
    if (wid == 0) TCGEN05_DEALLOC(tmem, 256);
#endif // CONV_HAS_TCGEN05
}

// ---------------- FFMA fallback ----------------

#define TILE_T 128
#define TT (TILE_T + 2)
#define XST (CF + 1)
#define FKc (CF * CK)
#define WST (FKc + 1)
#define FB_SMEM_BYTES ((CO * WST + TT * XST) * 4)

__global__ __launch_bounds__(256, 1)
void conv_fallback(const float* __restrict__ x, const float* __restrict__ w,
                   const float* __restrict__ bias, float* __restrict__ out)
{
    extern __shared__ float sh[];
    float* w_sh = sh;
    float* x_sh = sh + CO * WST;
    const int g  = blockIdx.x;
    const int t0 = blockIdx.y * TILE_T;
    const int b  = blockIdx.z;
    const int tid = threadIdx.x;
    const int tx = tid & 15, ty = tid >> 4;

    {
        const float4* wg = reinterpret_cast<const float4*>(w + (size_t)g * CO * FKc);
        #pragma unroll 4
        for (int idx = tid; idx < CO * FKc / 4; idx += 256) {
            int o = idx / (FKc / 4), c = idx - o * (FKc / 4);
            float4 v = wg[idx];
            float* d = &w_sh[o * WST + c * 4];
            d[0] = v.x; d[1] = v.y; d[2] = v.z; d[3] = v.w;
        }
    }
    {
        #pragma unroll 4
        for (int idx = tid; idx < TT * (CF / 4); idx += 256) {
            int r = idx / (CF / 4), c = idx - r * (CF / 4);
            int t = t0 - 1 + r;
            float4 v = make_float4(0.f, 0.f, 0.f, 0.f);
            if (t >= 0 && t < CT)
                v = reinterpret_cast<const float4*>(
                        x + ((size_t)(b * CT + t) * CG + g) * CF)[c];
            float* d = &x_sh[r * XST + c * 4];
            d[0] = v.x; d[1] = v.y; d[2] = v.z; d[3] = v.w;
        }
    }
    __syncthreads();

    float acc[8][6];
    #pragma unroll
    for (int i = 0; i < 8; i++)
        #pragma unroll
        for (int jj = 0; jj < 6; jj++) acc[i][jj] = 0.f;

    const int obase = tx * 6;
    #pragma unroll
    for (int k = 0; k < CK; k++) {
        const float* xp = &x_sh[(ty + k) * XST];
        const float* wp = &w_sh[obase * WST + k];
        #pragma unroll 2
        for (int f = 0; f < CF; f++) {
            float xr[8];
            #pragma unroll
            for (int i = 0; i < 8; i++) xr[i] = xp[i * 16 * XST + f];
            #pragma unroll
            for (int jj = 0; jj < 6; jj++) {
                float wv = wp[jj * WST + f * 3];
                #pragma unroll
                for (int i = 0; i < 8; i++) acc[i][jj] = fmaf(xr[i], wv, acc[i][jj]);
            }
        }
    }

    const float* bg = bias + g * CO + obase;
    float bv[6];
    #pragma unroll
    for (int jj = 0; jj < 6; jj++) bv[jj] = bg[jj];
    #pragma unroll
    for (int i = 0; i < 8; i++) {
        int t = t0 + ty + i * 16;
        float* op = out + ((size_t)(b * CT + t) * CG + g) * CO + obase;
        #pragma unroll
        for (int jj = 0; jj < 6; jj += 2) {
            float2 v2 = make_float2(acc[i][jj] + bv[jj], acc[i][jj + 1] + bv[jj + 1]);
            *reinterpret_cast<float2*>(op + jj) = v2;
        }
    }
}

// ---------------- launch ----------------

typedef CUresult (*EncodeTiledFn)(
    CUtensorMap*, CUtensorMapDataType, cuuint32_t, void*,
    const cuuint64_t*, const cuuint64_t*, const cuuint32_t*, const cuuint32_t*,
    CUtensorMapInterleave, CUtensorMapSwizzle, CUtensorMapL2promotion,
    CUtensorMapFloatOOBfill);

extern "C" void kernel_launch(void* const* d_in, const int* in_sizes, int n_in,
                              void* d_out, int out_size)
{
    const float* x    = (const float*)d_in[0];
    const float* w    = (const float*)d_in[1];
    const float* bias = (const float*)d_in[2];
    float* out        = (float*)d_out;

    cudaFuncAttributes attr{};
    cudaFuncGetAttributes(&attr, conv_mma);

    static EncodeTiledFn enc_fn = nullptr;
    static bool enc_tried = false;
    if (!enc_tried) {
        enc_tried = true;
        cudaDriverEntryPointQueryResult st;
        void* fn = nullptr;
        if (cudaGetDriverEntryPoint("cuTensorMapEncodeTiled", &fn,
                                    cudaEnableDefault, &st) == cudaSuccess &&
            st == cudaDriverEntryPointSuccess)
            enc_fn = (EncodeTiledFn)fn;
    }

    bool use_mma = (attr.numRegs >= 32) && (enc_fn != nullptr);
    CUtensorMap tmap{};
    if (use_mma) {
        cuuint64_t dims[4]    = {CF, CG, CT, CB};
        cuuint64_t strides[3] = {(cuuint64_t)CF * 4,
                                 (cuuint64_t)CG * CF * 4,
                                 (cuuint64_t)CT * CG * CF * 4};
        cuuint32_t box[4]     = {32, 1, 32, 1};      // 32-row sub-boxes
        cuuint32_t estr[4]    = {1, 1, 1, 1};
        CUresult r = enc_fn(&tmap, CU_TENSOR_MAP_DATA_TYPE_FLOAT32, 4, (void*)x,
                            dims, strides, box, estr,
                            CU_TENSOR_MAP_INTERLEAVE_NONE,
                            CU_TENSOR_MAP_SWIZZLE_128B,
                            CU_TENSOR_MAP_L2_PROMOTION_L2_128B,
                            CU_TENSOR_MAP_FLOAT_OOB_FILL_NONE);
        if (r != CUDA_SUCCESS) use_mma = false;
    }

    if (use_mma) {
        const int ntask = CG * CO * 288;
        prep_w<<<(ntask + 255) / 256, 256>>>(w);
        cudaFuncSetAttribute(conv_mma,
                             cudaFuncAttributeMaxDynamicSharedMemorySize, SMEM_TOTAL);
        conv_mma<<<CG, NTHREADS, SMEM_TOTAL>>>(tmap, bias, out);
    } else {
        cudaFuncSetAttribute(conv_fallback,
                             cudaFuncAttributeMaxDynamicSharedMemorySize, FB_SMEM_BYTES);
        dim3 grid(CG, CT / TILE_T, CB);
        conv_fallback<<<grid, 256, FB_SMEM_BYTES>>>(x, w, bias, out);
    }
}

// round 15
// speedup vs baseline: 2.0838x; 1.0841x over previous
#include <cuda_runtime.h>
#include <cuda.h>
#include <cstdint>

// Conv1dGroup as 129 tf32 tcgen05 GEMMs (sm_103a).
// Row-reduced ingest: per (tile, f-block) x is TMA-loaded ONCE (128-row box
// into the k=1 K-block + two 1-row halos, both at 1024-B-aligned SMEM so the
// SW128 permutation is identity), then 4 copy warps replicate it in SMEM at
// +-1 row shifts to build the k=0 / k=2 K-blocks of the unfolded K=288 A
// tile. MMA/epilogue identical to the proven double-buffered scheme.
// Warps: 4 epilogue + 1 MMA + 1 TMA + 4 copy = 320 threads.

#define CB 4
#define CT 512
#define CG 129
#define CF 96
#define CO 96
#define CK 3

#define ACOLT 12288                 // B bytes per 32-K atom col
#define NKB 9                       // 9 K blocks (K=288)
#define B_BYTES (NKB * ACOLT)       // 110592
#define UNITS 48                    // 16 tiles x 3 f-blocks
#define UNIT_SZ 51200               // 3 x 16384 blocks + 2 aligned halo slots
#define NTHREADS 320

#define SWZ(x) ((x) ^ (((x) >> 3) & 0x70))
#define IDESC_T ((1u<<4) | (2u<<7) | (2u<<10) | ((CO/8)<<17) | ((128/16)<<24))

// SMEM map (bytes)
#define SM_B       0
#define SM_U       110592           // 2 units x 51200 -> ends 212992
#define SM_BIAS    212992
#define SM_TMEMPTR 213376
#define SM_MBAR    213392
// ftma[2]@0,8  fcpy[2]@16,24  empty[2]@32,40  tile[2]@48,56  epi[2]@64,72  bok@80
#define SMEM_TOTAL 213504

// offsets inside a unit (halos 1024-aligned => SW128 identity for their row)
#define U_BLK(k)   ((k) * 16384)    // K-block for kernel tap k (TMA fills k=1)
#define U_HLO      49152            // halo row t0-1   (48*1024)
#define U_HHI      50176            // halo row t0+128 (49*1024)

#if defined(__CUDA_ARCH_FEAT_SM103_ALL) || defined(__CUDA_ARCH_FEAT_SM100_ALL)
#define CONV_HAS_TCGEN05 1
#else
#define CONV_HAS_TCGEN05 0
#endif

__device__ __align__(16) unsigned char g_wt[CG * B_BYTES];

static __device__ __forceinline__ uint32_t smem_u32(const void* p) {
    uint32_t a;
    asm("{ .reg .u64 t; cvta.to.shared.u64 t, %1; cvt.u32.u64 %0, t; }" : "=r"(a) : "l"(p));
    return a;
}

#define MBARRIER_INIT(addr, cnt) \
    asm volatile("mbarrier.init.shared.b64 [%0], %1;" :: "r"(addr), "r"(cnt) : "memory")
#define MBARRIER_INVAL(addr) \
    asm volatile("mbarrier.inval.shared.b64 [%0];" :: "r"(addr) : "memory")
#define MBARRIER_ARRIVE(addr) \
    asm volatile("mbarrier.arrive.shared.b64 _, [%0];" :: "r"((uint32_t)(addr)) : "memory")
#define MBARRIER_EXPECT_TX(addr, bytes) \
    asm volatile("mbarrier.arrive.expect_tx.shared.b64 _, [%0], %1;" \
                 :: "r"((uint32_t)(addr)), "r"((uint32_t)(bytes)) : "memory")
#define MBAR_WAIT(addr, parity, SEM) do {                                          \
    asm volatile(                                                                  \
        "{\n\t.reg .pred P;\n\t"                                                   \
        "WL_%=:\n\t"                                                               \
        "mbarrier.try_wait.parity." SEM ".cta.shared::cta.b64 P, [%0], %1, 0x989680;\n\t" \
        "@P bra.uni WD_%=;\n\t"                                                    \
        "bra.uni WL_%=;\n\t"                                                       \
        "WD_%=:\n\t}"                                                              \
        :: "r"((uint32_t)(addr)), "r"((uint32_t)(parity)) : "memory");             \
} while (0)
#define MBARRIER_WAIT_PARITY(a, p)  MBAR_WAIT(a, p, "acquire")
#define MBARRIER_WAIT_RELAXED(a, p) MBAR_WAIT(a, p, "relaxed")
#define FENCE_PROXY_ASYNC() asm volatile("fence.proxy.async.shared::cta;" ::: "memory")

#if CONV_HAS_TCGEN05

#define TCGEN05_ALLOC(smaddr, ncols) \
    asm volatile("tcgen05.alloc.cta_group::1.sync.aligned.shared::cta.b32 [%0], %1;" \
                 :: "r"((uint32_t)(smaddr)), "r"((uint32_t)(ncols)) : "memory")
#define TCGEN05_DEALLOC(tm, ncols) \
    asm volatile("tcgen05.dealloc.cta_group::1.sync.aligned.b32 %0, %1;" \
                 :: "r"(tm), "r"((uint32_t)(ncols)))
#define TCGEN05_COMMIT(mbar) \
    asm volatile("tcgen05.commit.cta_group::1.mbarrier::arrive::one.shared::cluster.b64 [%0];" \
                 :: "r"((uint32_t)(mbar)) : "memory")
#define TCGEN05_WAIT_LD() asm volatile("tcgen05.wait::ld.sync.aligned;" ::: "memory")
#define TCGEN05_FENCE_BEFORE() asm volatile("tcgen05.fence::before_thread_sync;" ::: "memory")
#define TCGEN05_FENCE_AFTER()  asm volatile("tcgen05.fence::after_thread_sync;" ::: "memory")

#define TCGEN05_LD_32X32B_X32(r, tmaddr) \
    asm volatile( \
        "tcgen05.ld.sync.aligned.32x32b.x32.b32 " \
        "{%0, %1, %2, %3, %4, %5, %6, %7, " \
        " %8, %9, %10, %11, %12, %13, %14, %15, " \
        " %16, %17, %18, %19, %20, %21, %22, %23, " \
        " %24, %25, %26, %27, %28, %29, %30, %31}, [%32];" \
        : "=r"((r)[0]),  "=r"((r)[1]),  "=r"((r)[2]),  "=r"((r)[3]), \
          "=r"((r)[4]),  "=r"((r)[5]),  "=r"((r)[6]),  "=r"((r)[7]), \
          "=r"((r)[8]),  "=r"((r)[9]),  "=r"((r)[10]), "=r"((r)[11]), \
          "=r"((r)[12]), "=r"((r)[13]), "=r"((r)[14]), "=r"((r)[15]), \
          "=r"((r)[16]), "=r"((r)[17]), "=r"((r)[18]), "=r"((r)[19]), \
          "=r"((r)[20]), "=r"((r)[21]), "=r"((r)[22]), "=r"((r)[23]), \
          "=r"((r)[24]), "=r"((r)[25]), "=r"((r)[26]), "=r"((r)[27]), \
          "=r"((r)[28]), "=r"((r)[29]), "=r"((r)[30]), "=r"((r)[31]) \
        : "r"(tmaddr))

#define TMA_LOAD_4D(smaddr, tmap, c0, c1, c2, c3, mbar) \
    asm volatile( \
        "cp.async.bulk.tensor.4d.shared::cta.global.tile.mbarrier::complete_tx::bytes " \
        "[%0], [%1, {%2, %3, %4, %5}], [%6];" \
        :: "r"((uint32_t)(smaddr)), "l"(tmap), "r"((int)(c0)), "r"((int)(c1)), \
           "r"((int)(c2)), "r"((int)(c3)), "r"((uint32_t)(mbar)) : "memory")

#define BULK_G2S(smaddr, gptr, bytes, mbar) \
    asm volatile( \
        "cp.async.bulk.shared::cta.global.mbarrier::complete_tx::bytes [%0], [%1], %2, [%3];" \
        :: "r"((uint32_t)(smaddr)), "l"(gptr), "r"((uint32_t)(bytes)), \
           "r"((uint32_t)(mbar)) : "memory")

static constexpr uint64_t SMEM_DESC_BASE_SW128 =
    (uint64_t(2) << 61) | (uint64_t(1) << 46) | (uint64_t(64) << 32) | (uint64_t(1) << 16);

static __device__ __forceinline__ uint64_t make_desc(uint32_t smaddr) {
    return SMEM_DESC_BASE_SW128 | ((uint64_t)(smaddr >> 4) & 0x3FFF);
}

static __device__ __forceinline__ void mma_tf32_ss(uint32_t d, uint64_t a, uint64_t b,
                                                   uint32_t idesc, uint32_t en) {
    asm volatile(
        "{\n\t.reg .pred p;\n\t"
        "setp.ne.u32 p, %4, 0;\n\t"
        "tcgen05.mma.cta_group::1.kind::tf32 [%0], %1, %2, %3, p;\n\t}"
        :: "r"(d), "l"(a), "l"(b), "r"(idesc), "r"(en) : "memory");
}

static __device__ __forceinline__ uint32_t elect_one() {
    uint32_t pred;
    asm volatile(
        "{\n\t.reg .pred p;\n\t"
        "elect.sync _|p, 0xFFFFFFFF;\n\t"
        "selp.b32 %0, 1, 0, p;\n\t}" : "=r"(pred));
    return pred;
}

#endif // CONV_HAS_TCGEN05

// -------- pre-kernel: weights -> tf32 (rna) in MMA SMEM layout --------

__global__ __launch_bounds__(256) void prep_w(const float* __restrict__ w) {
    int id = blockIdx.x * 256 + threadIdx.x;
    const int NTASK = CG * CO * 288;
    if (id >= NTASK) return;
    int K = id % 288;
    int o = (id / 288) % CO;
    int g = id / (288 * CO);
    int k = K / CF, f = K - CF * k;
    float v = w[(((size_t)(g * CO + o) * CF + f) * CK + k)];
    uint32_t t;
    asm("cvt.rna.tf32.f32 %0, %1;" : "=r"(t) : "f"(v));
    uint32_t addr = (uint32_t)g * B_BYTES + (K >> 5) * ACOLT + (o >> 3) * 1024
                  + SWZ(((o & 7) << 7) | ((K & 31) * 4));
    *(uint32_t*)(g_wt + addr) = t;
}

// ---------------- main kernel ----------------

__global__ __launch_bounds__(NTHREADS, 1)
void conv_mma(const __grid_constant__ CUtensorMap tmain,
              const __grid_constant__ CUtensorMap thalo,
              const float* __restrict__ bias, float* __restrict__ out)
{
#if CONV_HAS_TCGEN05
    extern __shared__ __align__(1024) unsigned char sm[];
    const uint32_t smb = smem_u32(sm);
    const int tid = threadIdx.x;
    const int g = blockIdx.x;
    const int wid = tid >> 5, lid = tid & 31;

    const uint32_t mb_ftma  = smb + SM_MBAR;          // +su*8
    const uint32_t mb_fcpy  = smb + SM_MBAR + 16;     // +su*8
    const uint32_t mb_empty = smb + SM_MBAR + 32;     // +su*8
    const uint32_t mb_tile  = smb + SM_MBAR + 48;     // +slot*8
    const uint32_t mb_epi   = smb + SM_MBAR + 64;     // +slot*8
    const uint32_t mb_bok   = smb + SM_MBAR + 80;

    if (tid == 0) {
        MBARRIER_INIT(mb_ftma + 0, 1);  MBARRIER_INIT(mb_ftma + 8, 1);
        MBARRIER_INIT(mb_fcpy + 0, 4);  MBARRIER_INIT(mb_fcpy + 8, 4);
        MBARRIER_INIT(mb_empty + 0, 1); MBARRIER_INIT(mb_empty + 8, 1);
        MBARRIER_INIT(mb_tile + 0, 1);  MBARRIER_INIT(mb_tile + 8, 1);
        MBARRIER_INIT(mb_epi + 0, 4);   MBARRIER_INIT(mb_epi + 8, 4);
        MBARRIER_INIT(mb_bok, 1);
    }
    if (tid < CO) ((float*)(sm + SM_BIAS))[tid] = bias[g * CO + tid];
    if (wid == 0) TCGEN05_ALLOC(smb + SM_TMEMPTR, 256);
    __syncthreads();

    uint32_t tmem;
    asm volatile("ld.shared.b32 %0, [%1];" : "=r"(tmem) : "r"(smb + SM_TMEMPTR));

    if (wid == 5) {
        // ============ TMA warp ============
        if (elect_one()) {
            MBARRIER_EXPECT_TX(mb_bok, B_BYTES);
            BULK_G2S(smb + SM_B, (const void*)(g_wt + (size_t)g * B_BYTES),
                     B_BYTES, mb_bok);
            for (int u = 0; u < UNITS; ++u) {
                const int su = u & 1;
                const int tile = u / 3, fb = u % 3;
                const int bb = tile >> 2, t0 = (tile & 3) << 7;
                const int f0 = fb * 32;
                if (u >= 2)
                    MBARRIER_WAIT_RELAXED(mb_empty + su * 8, ((u - 2) >> 1) & 1);
                const uint32_t ub = smb + SM_U + su * UNIT_SZ;
                MBARRIER_EXPECT_TX(mb_ftma + su * 8, 16384 + 256);
                TMA_LOAD_4D(ub + U_BLK(1), &tmain, f0, g, t0, bb, mb_ftma + su * 8);
                TMA_LOAD_4D(ub + U_HLO, &thalo, f0, g, t0 - 1, bb, mb_ftma + su * 8);
                TMA_LOAD_4D(ub + U_HHI, &thalo, f0, g, t0 + 128, bb, mb_ftma + su * 8);
            }
        }
    } else if (wid >= 6) {
        // ============ COPY warps (6..9): build k=0 / k=2 blocks ============
        const int cw = wid - 6;
        const int seg = lid & 7;
        const int rsub = lid >> 3;          // 0..3
        for (int u = 0; u < UNITS; ++u) {
            const int su = u & 1;
            MBARRIER_WAIT_PARITY(mb_ftma + su * 8, (u >> 1) & 1);
            unsigned char* ub = sm + SM_U + su * UNIT_SZ;
            unsigned char* mainb = ub + U_BLK(1);
            unsigned char* b0 = ub + U_BLK(0);
            unsigned char* b2 = ub + U_BLK(2);
            const unsigned char* hlo = ub + U_HLO;
            const unsigned char* hhi = ub + U_HHI;
            #pragma unroll
            for (int i = 0; i < 8; ++i) {
                const int row = cw * 32 + i * 4 + rsub;
                const uint32_t doff = ((uint32_t)(row >> 3) << 10)
                                    + SWZ((uint32_t)(((row & 7) << 7) | (seg << 4)));
                // k = 0 : rows shifted down (row 0 <- halo t0-1)
                {
                    const int sr = row - 1;
                    const unsigned char* sp = (row == 0)
                        ? hlo + (seg << 4)
                        : mainb + (((uint32_t)(sr >> 3)) << 10)
                                + SWZ((uint32_t)(((sr & 7) << 7) | (seg << 4)));
                    *(float4*)(b0 + doff) = *(const float4*)sp;
                }
                // k = 2 : rows shifted up (row 127 <- halo t0+128)
                {
                    const int sr = row + 1;
                    const unsigned char* sp = (row == 127)
                        ? hhi + (seg << 4)
                        : mainb + (((uint32_t)(sr >> 3)) << 10)
                                + SWZ((uint32_t)(((sr & 7) << 7) | (seg << 4)));
                    *(float4*)(b2 + doff) = *(const float4*)sp;
                }
            }
            FENCE_PROXY_ASYNC();
            __syncwarp();
            if (lid == 0) MBARRIER_ARRIVE(mb_fcpy + su * 8);
        }
    } else if (wid == 4) {
        // ============ MMA warp ============
        MBARRIER_WAIT_PARITY(mb_bok, 0);
        if (elect_one()) {
            int ph_epi[2] = {0, 0};
            for (int u = 0; u < UNITS; ++u) {
                const int su = u & 1;
                const int tile = u / 3, fb = u % 3;
                const int slot = tile & 1;
                const uint32_t dslot = tmem + (uint32_t)(slot * 128);
                MBARRIER_WAIT_PARITY(mb_fcpy + su * 8, (u >> 1) & 1);
                if (fb == 0 && tile >= 2) {
                    MBARRIER_WAIT_RELAXED(mb_epi + slot * 8, ph_epi[slot]);
                    ph_epi[slot] ^= 1;
                }
                const uint32_t ub = smb + SM_U + su * UNIT_SZ;
                #pragma unroll
                for (int k = 0; k < 3; ++k) {
                    const uint64_t ad = make_desc(ub + U_BLK(k));
                    const uint64_t bd = make_desc(smb + SM_B + (k * 3 + fb) * ACOLT);
                    #pragma unroll
                    for (int stp = 0; stp < 4; ++stp) {
                        uint32_t en = (fb > 0 || k > 0 || stp > 0) ? 1u : 0u;
                        mma_tf32_ss(dslot, ad + 2 * stp, bd + 2 * stp, IDESC_T, en);
                    }
                }
                TCGEN05_COMMIT(mb_empty + su * 8);
                if (fb == 2) TCGEN05_COMMIT(mb_tile + slot * 8);
            }
        }
    } else {
        // ============ EPILOGUE warps (0..3) ============
        const int sub = wid;
        int ph_t[2] = {0, 0};
        const float* bsm = (const float*)(sm + SM_BIAS);
        for (int tile = 0; tile < 16; ++tile) {
            const int slot = tile & 1;
            MBARRIER_WAIT_PARITY(mb_tile + slot * 8, ph_t[slot]);
            ph_t[slot] ^= 1;
            TCGEN05_FENCE_AFTER();
            const int trow = (tile & 3) * 128 + sub * 32 + lid;
            const int bb = tile >> 2;
            float* op = out + (((size_t)bb * CT + trow) * CG + g) * CO;
            const uint32_t D = tmem + (uint32_t)(slot * 128);
            #pragma unroll
            for (int bch = 0; bch < 3; ++bch) {
                uint32_t r[32];
                TCGEN05_LD_32X32B_X32(r, D + bch * 32);
                TCGEN05_WAIT_LD();
                #pragma unroll
                for (int q4 = 0; q4 < 8; ++q4) {
                    float4 bv = *(const float4*)(bsm + bch * 32 + q4 * 4);
                    float4 v;
                    v.x = __uint_as_float(r[q4 * 4 + 0]) + bv.x;
                    v.y = __uint_as_float(r[q4 * 4 + 1]) + bv.y;
                    v.z = __uint_as_float(r[q4 * 4 + 2]) + bv.z;
                    v.w = __uint_as_float(r[q4 * 4 + 3]) + bv.w;
                    *(float4*)(op + bch * 32 + q4 * 4) = v;
                }
            }
            TCGEN05_FENCE_BEFORE();
            __syncwarp();
            if (lid == 0) MBARRIER_ARRIVE(mb_epi + slot * 8);
        }
    }

    __syncthreads();
    if (tid == 0) {
        MBARRIER_INVAL(mb_ftma + 0);  MBARRIER_INVAL(mb_ftma + 8);
        MBARRIER_INVAL(mb_fcpy + 0);  MBARRIER_INVAL(mb_fcpy + 8);
        MBARRIER_INVAL(mb_empty + 0); MBARRIER_INVAL(mb_empty + 8);
        MBARRIER_INVAL(mb_tile + 0);  MBARRIER_INVAL(mb_tile + 8);
        MBARRIER_INVAL(mb_epi + 0);   MBARRIER_INVAL(mb_epi + 8);
        MBARRIER_INVAL(mb_bok);
    }
    __syncthreads();
    if (wid == 0) TCGEN05_DEALLOC(tmem, 256);
#endif // CONV_HAS_TCGEN05
}

// ---------------- FFMA fallback ----------------

#define TILE_T 128
#define TT (TILE_T + 2)
#define XST (CF + 1)
#define FKc (CF * CK)
#define WST (FKc + 1)
#define FB_SMEM_BYTES ((CO * WST + TT * XST) * 4)

__global__ __launch_bounds__(256, 1)
void conv_fallback(const float* __restrict__ x, const float* __restrict__ w,
                   const float* __restrict__ bias, float* __restrict__ out)
{
    extern __shared__ float sh[];
    float* w_sh = sh;
    float* x_sh = sh + CO * WST;
    const int g  = blockIdx.x;
    const int t0 = blockIdx.y * TILE_T;
    const int b  = blockIdx.z;
    const int tid = threadIdx.x;
    const int tx = tid & 15, ty = tid >> 4;

    {
        const float4* wg = reinterpret_cast<const float4*>(w + (size_t)g * CO * FKc);
        #pragma unroll 4
        for (int idx = tid; idx < CO * FKc / 4; idx += 256) {
            int o = idx / (FKc / 4), c = idx - o * (FKc / 4);
            float4 v = wg[idx];
            float* d = &w_sh[o * WST + c * 4];
            d[0] = v.x; d[1] = v.y; d[2] = v.z; d[3] = v.w;
        }
    }
    {
        #pragma unroll 4
        for (int idx = tid; idx < TT * (CF / 4); idx += 256) {
            int r = idx / (CF / 4), c = idx - r * (CF / 4);
            int t = t0 - 1 + r;
            float4 v = make_float4(0.f, 0.f, 0.f, 0.f);
            if (t >= 0 && t < CT)
                v = reinterpret_cast<const float4*>(
                        x + ((size_t)(b * CT + t) * CG + g) * CF)[c];
            float* d = &x_sh[r * XST + c * 4];
            d[0] = v.x; d[1] = v.y; d[2] = v.z; d[3] = v.w;
        }
    }
    __syncthreads();

    float acc[8][6];
    #pragma unroll
    for (int i = 0; i < 8; i++)
        #pragma unroll
        for (int jj = 0; jj < 6; jj++) acc[i][jj] = 0.f;

    const int obase = tx * 6;
    #pragma unroll
    for (int k = 0; k < CK; k++) {
        const float* xp = &x_sh[(ty + k) * XST];
        const float* wp = &w_sh[obase * WST + k];
        #pragma unroll 2
        for (int f = 0; f < CF; f++) {
            float xr[8];
            #pragma unroll
            for (int i = 0; i < 8; i++) xr[i] = xp[i * 16 * XST + f];
            #pragma unroll
            for (int jj = 0; jj < 6; jj++) {
                float wv = wp[jj * WST + f * 3];
                #pragma unroll
                for (int i = 0; i < 8; i++) acc[i][jj] = fmaf(xr[i], wv, acc[i][jj]);
            }
        }
    }

    const float* bg = bias + g * CO + obase;
    float bv[6];
    #pragma unroll
    for (int jj = 0; jj < 6; jj++) bv[jj] = bg[jj];
    #pragma unroll
    for (int i = 0; i < 8; i++) {
        int t = t0 + ty + i * 16;
        float* op = out + ((size_t)(b * CT + t) * CG + g) * CO + obase;
        #pragma unroll
        for (int jj = 0; jj < 6; jj += 2) {
            float2 v2 = make_float2(acc[i][jj] + bv[jj], acc[i][jj + 1] + bv[jj + 1]);
            *reinterpret_cast<float2*>(op + jj) = v2;
        }
    }
}

// ---------------- launch ----------------

typedef CUresult (*EncodeTiledFn)(
    CUtensorMap*, CUtensorMapDataType, cuuint32_t, void*,
    const cuuint64_t*, const cuuint64_t*, const cuuint32_t*, const cuuint32_t*,
    CUtensorMapInterleave, CUtensorMapSwizzle, CUtensorMapL2promotion,
    CUtensorMapFloatOOBfill);

extern "C" void kernel_launch(void* const* d_in, const int* in_sizes, int n_in,
                              void* d_out, int out_size)
{
    const float* x    = (const float*)d_in[0];
    const float* w    = (const float*)d_in[1];
    const float* bias = (const float*)d_in[2];
    float* out        = (float*)d_out;

    cudaFuncAttributes attr{};
    cudaFuncGetAttributes(&attr, conv_mma);

    static EncodeTiledFn enc_fn = nullptr;
    static bool enc_tried = false;
    if (!enc_tried) {
        enc_tried = true;
        cudaDriverEntryPointQueryResult st;
        void* fn = nullptr;
        if (cudaGetDriverEntryPoint("cuTensorMapEncodeTiled", &fn,
                                    cudaEnableDefault, &st) == cudaSuccess &&
            st == cudaDriverEntryPointSuccess)
            enc_fn = (EncodeTiledFn)fn;
    }

    bool use_mma = (attr.numRegs >= 32) && (enc_fn != nullptr);
    CUtensorMap tmain{}, thalo{};
    if (use_mma) {
        cuuint64_t dims[4]    = {CF, CG, CT, CB};
        cuuint64_t strides[3] = {(cuuint64_t)CF * 4,
                                 (cuuint64_t)CG * CF * 4,
                                 (cuuint64_t)CT * CG * CF * 4};
        cuuint32_t estr[4]    = {1, 1, 1, 1};
        cuuint32_t box_m[4]   = {32, 1, 128, 1};
        cuuint32_t box_h[4]   = {32, 1, 1, 1};
        CUresult r1 = enc_fn(&tmain, CU_TENSOR_MAP_DATA_TYPE_FLOAT32, 4, (void*)x,
                             dims, strides, box_m, estr,
                             CU_TENSOR_MAP_INTERLEAVE_NONE,
                             CU_TENSOR_MAP_SWIZZLE_128B,
                             CU_TENSOR_MAP_L2_PROMOTION_L2_128B,
                             CU_TENSOR_MAP_FLOAT_OOB_FILL_NONE);
        CUresult r2 = enc_fn(&thalo, CU_TENSOR_MAP_DATA_TYPE_FLOAT32, 4, (void*)x,
                             dims, strides, box_h, estr,
                             CU_TENSOR_MAP_INTERLEAVE_NONE,
                             CU_TENSOR_MAP_SWIZZLE_128B,
                             CU_TENSOR_MAP_L2_PROMOTION_L2_128B,
                             CU_TENSOR_MAP_FLOAT_OOB_FILL_NONE);
        if (r1 != CUDA_SUCCESS || r2 != CUDA_SUCCESS) use_mma = false;
    }

    if (use_mma) {
        const int ntask = CG * CO * 288;
        prep_w<<<(ntask + 255) / 256, 256>>>(w);
        cudaFuncSetAttribute(conv_mma,
                             cudaFuncAttributeMaxDynamicSharedMemorySize, SMEM_TOTAL);
        conv_mma<<<CG, NTHREADS, SMEM_TOTAL>>>(tmain, thalo, bias, out);
    } else {
        cudaFuncSetAttribute(conv_fallback,
                             cudaFuncAttributeMaxDynamicSharedMemorySize, FB_SMEM_BYTES);
        dim3 grid(CG, CT / TILE_T, CB);
        conv_fallback<<<grid, 256, FB_SMEM_BYTES>>>(x, w, bias, out);
    }
}

// round 16
// speedup vs baseline: 2.4038x; 1.1536x over previous
#include <cuda_runtime.h>
#include <cuda.h>
#include <cstdint>

// Conv1dGroup as 129 tf32 tcgen05 GEMMs (sm_103a).
// Zero-copy tap unfold: per (tile, f-block) x rows t0-1..t0+128 (130 rows,
// OOB zero) are TMA-loaded once into a 1024-aligned SMEM buffer; kernel tap
// k's MMAs use an A descriptor starting at base + k*128B (SW128 swizzle is
// absolute-address based for both TMA writes and MMA descriptor reads, so
// the +-1-row shifted views need no data movement). 6-deep ring.
// Warps: 4 epilogue + 1 MMA + 1 TMA = 192 threads.

#define CB 4
#define CT 512
#define CG 129
#define CF 96
#define CO 96
#define CK 3

#define ACOLT 12288                 // B bytes per 32-K atom col
#define NKB 9                       // 9 K blocks (K=288)
#define B_BYTES (NKB * ACOLT)       // 110592
#define UNITS 48                    // 16 tiles x 3 f-blocks
#define UNIT_SZ 17408               // 130 rows x 128 B, padded to 1024
#define UNIT_TX 16640               // bytes actually delivered per unit
#define NBUF 6
#define NTHREADS 192

#define SWZ(x) ((x) ^ (((x) >> 3) & 0x70))
#define IDESC_T ((1u<<4) | (2u<<7) | (2u<<10) | ((CO/8)<<17) | ((128/16)<<24))

// SMEM map (bytes)
#define SM_B       0
#define SM_A       110592           // 6 x 17408 = 104448 -> ends 215040
#define SM_BIAS    215040
#define SM_TMEMPTR 215424
#define SM_MBAR    215440
// full[6]@0..47  empty[6]@48..95  tile[2]@96,104  epi[2]@112,120  bok@128
#define SMEM_TOTAL 215808

#if defined(__CUDA_ARCH_FEAT_SM103_ALL) || defined(__CUDA_ARCH_FEAT_SM100_ALL)
#define CONV_HAS_TCGEN05 1
#else
#define CONV_HAS_TCGEN05 0
#endif

__device__ __align__(16) unsigned char g_wt[CG * B_BYTES];

static __device__ __forceinline__ uint32_t smem_u32(const void* p) {
    uint32_t a;
    asm("{ .reg .u64 t; cvta.to.shared.u64 t, %1; cvt.u32.u64 %0, t; }" : "=r"(a) : "l"(p));
    return a;
}

#define MBARRIER_INIT(addr, cnt) \
    asm volatile("mbarrier.init.shared.b64 [%0], %1;" :: "r"(addr), "r"(cnt) : "memory")
#define MBARRIER_INVAL(addr) \
    asm volatile("mbarrier.inval.shared.b64 [%0];" :: "r"(addr) : "memory")
#define MBARRIER_ARRIVE(addr) \
    asm volatile("mbarrier.arrive.shared.b64 _, [%0];" :: "r"((uint32_t)(addr)) : "memory")
#define MBARRIER_EXPECT_TX(addr, bytes) \
    asm volatile("mbarrier.arrive.expect_tx.shared.b64 _, [%0], %1;" \
                 :: "r"((uint32_t)(addr)), "r"((uint32_t)(bytes)) : "memory")
#define MBAR_WAIT(addr, parity, SEM) do {                                          \
    asm volatile(                                                                  \
        "{\n\t.reg .pred P;\n\t"                                                   \
        "WL_%=:\n\t"                                                               \
        "mbarrier.try_wait.parity." SEM ".cta.shared::cta.b64 P, [%0], %1, 0x989680;\n\t" \
        "@P bra.uni WD_%=;\n\t"                                                    \
        "bra.uni WL_%=;\n\t"                                                       \
        "WD_%=:\n\t}"                                                              \
        :: "r"((uint32_t)(addr)), "r"((uint32_t)(parity)) : "memory");             \
} while (0)
#define MBARRIER_WAIT_PARITY(a, p)  MBAR_WAIT(a, p, "acquire")
#define MBARRIER_WAIT_RELAXED(a, p) MBAR_WAIT(a, p, "relaxed")

#if CONV_HAS_TCGEN05

#define TCGEN05_ALLOC(smaddr, ncols) \
    asm volatile("tcgen05.alloc.cta_group::1.sync.aligned.shared::cta.b32 [%0], %1;" \
                 :: "r"((uint32_t)(smaddr)), "r"((uint32_t)(ncols)) : "memory")
#define TCGEN05_DEALLOC(tm, ncols) \
    asm volatile("tcgen05.dealloc.cta_group::1.sync.aligned.b32 %0, %1;" \
                 :: "r"(tm), "r"((uint32_t)(ncols)))
#define TCGEN05_COMMIT(mbar) \
    asm volatile("tcgen05.commit.cta_group::1.mbarrier::arrive::one.shared::cluster.b64 [%0];" \
                 :: "r"((uint32_t)(mbar)) : "memory")
#define TCGEN05_WAIT_LD() asm volatile("tcgen05.wait::ld.sync.aligned;" ::: "memory")
#define TCGEN05_FENCE_BEFORE() asm volatile("tcgen05.fence::before_thread_sync;" ::: "memory")
#define TCGEN05_FENCE_AFTER()  asm volatile("tcgen05.fence::after_thread_sync;" ::: "memory")

#define TCGEN05_LD_32X32B_X32(r, tmaddr) \
    asm volatile( \
        "tcgen05.ld.sync.aligned.32x32b.x32.b32 " \
        "{%0, %1, %2, %3, %4, %5, %6, %7, " \
        " %8, %9, %10, %11, %12, %13, %14, %15, " \
        " %16, %17, %18, %19, %20, %21, %22, %23, " \
        " %24, %25, %26, %27, %28, %29, %30, %31}, [%32];" \
        : "=r"((r)[0]),  "=r"((r)[1]),  "=r"((r)[2]),  "=r"((r)[3]), \
          "=r"((r)[4]),  "=r"((r)[5]),  "=r"((r)[6]),  "=r"((r)[7]), \
          "=r"((r)[8]),  "=r"((r)[9]),  "=r"((r)[10]), "=r"((r)[11]), \
          "=r"((r)[12]), "=r"((r)[13]), "=r"((r)[14]), "=r"((r)[15]), \
          "=r"((r)[16]), "=r"((r)[17]), "=r"((r)[18]), "=r"((r)[19]), \
          "=r"((r)[20]), "=r"((r)[21]), "=r"((r)[22]), "=r"((r)[23]), \
          "=r"((r)[24]), "=r"((r)[25]), "=r"((r)[26]), "=r"((r)[27]), \
          "=r"((r)[28]), "=r"((r)[29]), "=r"((r)[30]), "=r"((r)[31]) \
        : "r"(tmaddr))

#define TMA_LOAD_4D(smaddr, tmap, c0, c1, c2, c3, mbar) \
    asm volatile( \
        "cp.async.bulk.tensor.4d.shared::cta.global.tile.mbarrier::complete_tx::bytes " \
        "[%0], [%1, {%2, %3, %4, %5}], [%6];" \
        :: "r"((uint32_t)(smaddr)), "l"(tmap), "r"((int)(c0)), "r"((int)(c1)), \
           "r"((int)(c2)), "r"((int)(c3)), "r"((uint32_t)(mbar)) : "memory")

#define BULK_G2S(smaddr, gptr, bytes, mbar) \
    asm volatile( \
        "cp.async.bulk.shared::cta.global.mbarrier::complete_tx::bytes [%0], [%1], %2, [%3];" \
        :: "r"((uint32_t)(smaddr)), "l"(gptr), "r"((uint32_t)(bytes)), \
           "r"((uint32_t)(mbar)) : "memory")

static constexpr uint64_t SMEM_DESC_BASE_SW128 =
    (uint64_t(2) << 61) | (uint64_t(1) << 46) | (uint64_t(64) << 32) | (uint64_t(1) << 16);

static __device__ __forceinline__ uint64_t make_desc(uint32_t smaddr) {
    return SMEM_DESC_BASE_SW128 | ((uint64_t)(smaddr >> 4) & 0x3FFF);
}

static __device__ __forceinline__ void mma_tf32_ss(uint32_t d, uint64_t a, uint64_t b,
                                                   uint32_t idesc, uint32_t en) {
    asm volatile(
        "{\n\t.reg .pred p;\n\t"
        "setp.ne.u32 p, %4, 0;\n\t"
        "tcgen05.mma.cta_group::1.kind::tf32 [%0], %1, %2, %3, p;\n\t}"
        :: "r"(d), "l"(a), "l"(b), "r"(idesc), "r"(en) : "memory");
}

static __device__ __forceinline__ uint32_t elect_one() {
    uint32_t pred;
    asm volatile(
        "{\n\t.reg .pred p;\n\t"
        "elect.sync _|p, 0xFFFFFFFF;\n\t"
        "selp.b32 %0, 1, 0, p;\n\t}" : "=r"(pred));
    return pred;
}

#endif // CONV_HAS_TCGEN05

// -------- pre-kernel: weights -> tf32 (rna) in MMA SMEM layout --------

__global__ __launch_bounds__(256) void prep_w(const float* __restrict__ w) {
    int id = blockIdx.x * 256 + threadIdx.x;
    const int NTASK = CG * CO * 288;
    if (id >= NTASK) return;
    int K = id % 288;
    int o = (id / 288) % CO;
    int g = id / (288 * CO);
    int k = K / CF, f = K - CF * k;
    float v = w[(((size_t)(g * CO + o) * CF + f) * CK + k)];
    uint32_t t;
    asm("cvt.rna.tf32.f32 %0, %1;" : "=r"(t) : "f"(v));
    uint32_t addr = (uint32_t)g * B_BYTES + (K >> 5) * ACOLT + (o >> 3) * 1024
                  + SWZ(((o & 7) << 7) | ((K & 31) * 4));
    *(uint32_t*)(g_wt + addr) = t;
}

// ---------------- main kernel ----------------

__global__ __launch_bounds__(NTHREADS, 1)
void conv_mma(const __grid_constant__ CUtensorMap tmap,
              const float* __restrict__ bias, float* __restrict__ out)
{
#if CONV_HAS_TCGEN05
    extern __shared__ __align__(1024) unsigned char sm[];
    const uint32_t smb = smem_u32(sm);
    const int tid = threadIdx.x;
    const int g = blockIdx.x;
    const int wid = tid >> 5, lid = tid & 31;

    const uint32_t mb_full  = smb + SM_MBAR;          // +s*8, s<6
    const uint32_t mb_empty = smb + SM_MBAR + 48;     // +s*8
    const uint32_t mb_tile  = smb + SM_MBAR + 96;     // +slot*8
    const uint32_t mb_epi   = smb + SM_MBAR + 112;    // +slot*8
    const uint32_t mb_bok   = smb + SM_MBAR + 128;

    if (tid == 0) {
        #pragma unroll
        for (int s = 0; s < NBUF; ++s) {
            MBARRIER_INIT(mb_full + s * 8, 1);
            MBARRIER_INIT(mb_empty + s * 8, 1);
        }
        MBARRIER_INIT(mb_tile + 0, 1);
        MBARRIER_INIT(mb_tile + 8, 1);
        MBARRIER_INIT(mb_epi + 0, 4);
        MBARRIER_INIT(mb_epi + 8, 4);
        MBARRIER_INIT(mb_bok, 1);
    }
    if (tid < CO) ((float*)(sm + SM_BIAS))[tid] = bias[g * CO + tid];
    if (wid == 0) TCGEN05_ALLOC(smb + SM_TMEMPTR, 256);
    __syncthreads();

    uint32_t tmem;
    asm volatile("ld.shared.b32 %0, [%1];" : "=r"(tmem) : "r"(smb + SM_TMEMPTR));

    if (wid == 5) {
        // ============ TMA warp: one 130-row box per unit ============
        if (elect_one()) {
            MBARRIER_EXPECT_TX(mb_bok, B_BYTES);
            BULK_G2S(smb + SM_B, (const void*)(g_wt + (size_t)g * B_BYTES),
                     B_BYTES, mb_bok);
            int ph_e[NBUF] = {0,0,0,0,0,0};
            for (int u = 0; u < UNITS; ++u) {
                const int s = u % NBUF;
                const int tile = u / 3, fb = u % 3;
                const int bb = tile >> 2, t0 = (tile & 3) << 7;
                if (u >= NBUF) {
                    MBARRIER_WAIT_RELAXED(mb_empty + s * 8, ph_e[s]);
                    ph_e[s] ^= 1;
                }
                MBARRIER_EXPECT_TX(mb_full + s * 8, UNIT_TX);
                TMA_LOAD_4D(smb + SM_A + s * UNIT_SZ, &tmap,
                            fb * 32, g, t0 - 1, bb, mb_full + s * 8);
            }
        }
    } else if (wid == 4) {
        // ============ MMA warp: 3 taps via descriptor row offsets ============
        MBARRIER_WAIT_PARITY(mb_bok, 0);
        if (elect_one()) {
            int ph_f[NBUF] = {0,0,0,0,0,0};
            int ph_epi[2] = {0, 0};
            for (int u = 0; u < UNITS; ++u) {
                const int s = u % NBUF;
                const int tile = u / 3, fb = u % 3;
                const int slot = tile & 1;
                const uint32_t dslot = tmem + (uint32_t)(slot * 128);
                MBARRIER_WAIT_RELAXED(mb_full + s * 8, ph_f[s]);
                ph_f[s] ^= 1;
                if (fb == 0 && tile >= 2) {
                    MBARRIER_WAIT_RELAXED(mb_epi + slot * 8, ph_epi[slot]);
                    ph_epi[slot] ^= 1;
                }
                const uint32_t ub = smb + SM_A + s * UNIT_SZ;
                #pragma unroll
                for (int k = 0; k < 3; ++k) {
                    // tap k: A rows start one row deeper per k (zero-copy shift)
                    const uint64_t ad = make_desc(ub + (uint32_t)(k * 128));
                    const uint64_t bd = make_desc(smb + SM_B + (k * 3 + fb) * ACOLT);
                    #pragma unroll
                    for (int stp = 0; stp < 4; ++stp) {
                        uint32_t en = (fb > 0 || k > 0 || stp > 0) ? 1u : 0u;
                        mma_tf32_ss(dslot, ad + 2 * stp, bd + 2 * stp, IDESC_T, en);
                    }
                }
                TCGEN05_COMMIT(mb_empty + s * 8);
                if (fb == 2) TCGEN05_COMMIT(mb_tile + slot * 8);
            }
        }
    } else {
        // ============ EPILOGUE warps (0..3) ============
        const int sub = wid;
        int ph_t[2] = {0, 0};
        const float* bsm = (const float*)(sm + SM_BIAS);
        for (int tile = 0; tile < 16; ++tile) {
            const int slot = tile & 1;
            MBARRIER_WAIT_PARITY(mb_tile + slot * 8, ph_t[slot]);
            ph_t[slot] ^= 1;
            TCGEN05_FENCE_AFTER();
            const int trow = (tile & 3) * 128 + sub * 32 + lid;
            const int bb = tile >> 2;
            float* op = out + (((size_t)bb * CT + trow) * CG + g) * CO;
            const uint32_t D = tmem + (uint32_t)(slot * 128);
            #pragma unroll
            for (int bch = 0; bch < 3; ++bch) {
                uint32_t r[32];
                TCGEN05_LD_32X32B_X32(r, D + bch * 32);
                TCGEN05_WAIT_LD();
                #pragma unroll
                for (int q4 = 0; q4 < 8; ++q4) {
                    float4 bv = *(const float4*)(bsm + bch * 32 + q4 * 4);
                    float4 v;
                    v.x = __uint_as_float(r[q4 * 4 + 0]) + bv.x;
                    v.y = __uint_as_float(r[q4 * 4 + 1]) + bv.y;
                    v.z = __uint_as_float(r[q4 * 4 + 2]) + bv.z;
                    v.w = __uint_as_float(r[q4 * 4 + 3]) + bv.w;
                    *(float4*)(op + bch * 32 + q4 * 4) = v;
                }
            }
            TCGEN05_FENCE_BEFORE();
            __syncwarp();
            if (lid == 0) MBARRIER_ARRIVE(mb_epi + slot * 8);
        }
    }

    __syncthreads();
    if (tid == 0) {
        #pragma unroll
        for (int s = 0; s < NBUF; ++s) {
            MBARRIER_INVAL(mb_full + s * 8);
            MBARRIER_INVAL(mb_empty + s * 8);
        }
        MBARRIER_INVAL(mb_tile + 0); MBARRIER_INVAL(mb_tile + 8);
        MBARRIER_INVAL(mb_epi + 0);  MBARRIER_INVAL(mb_epi + 8);
        MBARRIER_INVAL(mb_bok);
    }
    __syncthreads();
    if (wid == 0) TCGEN05_DEALLOC(tmem, 256);
#endif // CONV_HAS_TCGEN05
}

// ---------------- FFMA fallback ----------------

#define TILE_T 128
#define TT (TILE_T + 2)
#define XST (CF + 1)
#define FKc (CF * CK)
#define WST (FKc + 1)
#define FB_SMEM_BYTES ((CO * WST + TT * XST) * 4)

__global__ __launch_bounds__(256, 1)
void conv_fallback(const float* __restrict__ x, const float* __restrict__ w,
                   const float* __restrict__ bias, float* __restrict__ out)
{
    extern __shared__ float sh[];
    float* w_sh = sh;
    float* x_sh = sh + CO * WST;
    const int g  = blockIdx.x;
    const int t0 = blockIdx.y * TILE_T;
    const int b  = blockIdx.z;
    const int tid = threadIdx.x;
    const int tx = tid & 15, ty = tid >> 4;

    {
        const float4* wg = reinterpret_cast<const float4*>(w + (size_t)g * CO * FKc);
        #pragma unroll 4
        for (int idx = tid; idx < CO * FKc / 4; idx += 256) {
            int o = idx / (FKc / 4), c = idx - o * (FKc / 4);
            float4 v = wg[idx];
            float* d = &w_sh[o * WST + c * 4];
            d[0] = v.x; d[1] = v.y; d[2] = v.z; d[3] = v.w;
        }
    }
    {
        #pragma unroll 4
        for (int idx = tid; idx < TT * (CF / 4); idx += 256) {
            int r = idx / (CF / 4), c = idx - r * (CF / 4);
            int t = t0 - 1 + r;
            float4 v = make_float4(0.f, 0.f, 0.f, 0.f);
            if (t >= 0 && t < CT)
                v = reinterpret_cast<const float4*>(
                        x + ((size_t)(b * CT + t) * CG + g) * CF)[c];
            float* d = &x_sh[r * XST + c * 4];
            d[0] = v.x; d[1] = v.y; d[2] = v.z; d[3] = v.w;
        }
    }
    __syncthreads();

    float acc[8][6];
    #pragma unroll
    for (int i = 0; i < 8; i++)
        #pragma unroll
        for (int jj = 0; jj < 6; jj++) acc[i][jj] = 0.f;

    const int obase = tx * 6;
    #pragma unroll
    for (int k = 0; k < CK; k++) {
        const float* xp = &x_sh[(ty + k) * XST];
        const float* wp = &w_sh[obase * WST + k];
        #pragma unroll 2
        for (int f = 0; f < CF; f++) {
            float xr[8];
            #pragma unroll
            for (int i = 0; i < 8; i++) xr[i] = xp[i * 16 * XST + f];
            #pragma unroll
            for (int jj = 0; jj < 6; jj++) {
                float wv = wp[jj * WST + f * 3];
                #pragma unroll
                for (int i = 0; i < 8; i++) acc[i][jj] = fmaf(xr[i], wv, acc[i][jj]);
            }
        }
    }

    const float* bg = bias + g * CO + obase;
    float bv[6];
    #pragma unroll
    for (int jj = 0; jj < 6; jj++) bv[jj] = bg[jj];
    #pragma unroll
    for (int i = 0; i < 8; i++) {
        int t = t0 + ty + i * 16;
        float* op = out + ((size_t)(b * CT + t) * CG + g) * CO + obase;
        #pragma unroll
        for (int jj = 0; jj < 6; jj += 2) {
            float2 v2 = make_float2(acc[i][jj] + bv[jj], acc[i][jj + 1] + bv[jj + 1]);
            *reinterpret_cast<float2*>(op + jj) = v2;
        }
    }
}

// ---------------- launch ----------------

typedef CUresult (*EncodeTiledFn)(
    CUtensorMap*, CUtensorMapDataType, cuuint32_t, void*,
    const cuuint64_t*, const cuuint64_t*, const cuuint32_t*, const cuuint32_t*,
    CUtensorMapInterleave, CUtensorMapSwizzle, CUtensorMapL2promotion,
    CUtensorMapFloatOOBfill);

extern "C" void kernel_launch(void* const* d_in, const int* in_sizes, int n_in,
                              void* d_out, int out_size)
{
    const float* x    = (const float*)d_in[0];
    const float* w    = (const float*)d_in[1];
    const float* bias = (const float*)d_in[2];
    float* out        = (float*)d_out;

    cudaFuncAttributes attr{};
    cudaFuncGetAttributes(&attr, conv_mma);

    static EncodeTiledFn enc_fn = nullptr;
    static bool enc_tried = false;
    if (!enc_tried) {
        enc_tried = true;
        cudaDriverEntryPointQueryResult st;
        void* fn = nullptr;
        if (cudaGetDriverEntryPoint("cuTensorMapEncodeTiled", &fn,
                                    cudaEnableDefault, &st) == cudaSuccess &&
            st == cudaDriverEntryPointSuccess)
            enc_fn = (EncodeTiledFn)fn;
    }

    bool use_mma = (attr.numRegs >= 32) && (enc_fn != nullptr);
    CUtensorMap tmap{};
    if (use_mma) {
        cuuint64_t dims[4]    = {CF, CG, CT, CB};
        cuuint64_t strides[3] = {(cuuint64_t)CF * 4,
                                 (cuuint64_t)CG * CF * 4,
                                 (cuuint64_t)CT * CG * CF * 4};
        cuuint32_t box[4]     = {32, 1, 130, 1};     // 130-row halo-inclusive box
        cuuint32_t estr[4]    = {1, 1, 1, 1};
        CUresult r = enc_fn(&tmap, CU_TENSOR_MAP_DATA_TYPE_FLOAT32, 4, (void*)x,
                            dims, strides, box, estr,
                            CU_TENSOR_MAP_INTERLEAVE_NONE,
                            CU_TENSOR_MAP_SWIZZLE_128B,
                            CU_TENSOR_MAP_L2_PROMOTION_L2_128B,
                            CU_TENSOR_MAP_FLOAT_OOB_FILL_NONE);
        if (r != CUDA_SUCCESS) use_mma = false;
    }

    if (use_mma) {
        const int ntask = CG * CO * 288;
        prep_w<<<(ntask + 255) / 256, 256>>>(w);
        cudaFuncSetAttribute(conv_mma,
                             cudaFuncAttributeMaxDynamicSharedMemorySize, SMEM_TOTAL);
        conv_mma<<<CG, NTHREADS, SMEM_TOTAL>>>(tmap, bias, out);
    } else {
        cudaFuncSetAttribute(conv_fallback,
                             cudaFuncAttributeMaxDynamicSharedMemorySize, FB_SMEM_BYTES);
        dim3 grid(CG, CT / TILE_T, CB);
        conv_fallback<<<grid, 256, FB_SMEM_BYTES>>>(x, w, bias, out);
    }
}